// round 1
// baseline (speedup 1.0000x reference)
#include <cuda_runtime.h>
#include <math.h>

// Problem constants
#define BATCH 256
#define NV    196
#define LT    32
#define CV    768
#define CT    512
#define CI    768
#define NHEAD 12
#define DHEAD 64

#define MQ  (BATCH*NV)   // 50176 query rows
#define MKV (BATCH*LT)   // 8192 kv rows

// Scratch (allocation-free rule: __device__ globals)
__device__ float g_q[(size_t)MQ * CI];
__device__ float g_k[(size_t)MKV * CI];
__device__ float g_v[(size_t)MKV * CI];
__device__ float g_fused[(size_t)MQ * CI];
__device__ float g_hidden[(size_t)MQ * CI];

// ---------------------------------------------------------------------------
// Generic 64x64x16 register-tiled GEMM: C = A[M,K] * B[K,N] + bias, optional
// quick-gelu epilogue. M,N multiples of 64; K multiple of 16 (true for all
// our shapes, so no bounds checks).
// ---------------------------------------------------------------------------
template <bool GELU>
__global__ void __launch_bounds__(256, 2)
gemm_bias_kernel(const float* __restrict__ A, const float* __restrict__ B,
                 const float* __restrict__ bias, float* __restrict__ C,
                 int M, int N, int K)
{
    __shared__ float As[16][68];   // transposed A tile, padded
    __shared__ float Bs[16][64];

    const int tx = threadIdx.x & 15;   // 0..15 -> 4 cols each
    const int ty = threadIdx.x >> 4;   // 0..15 -> 4 rows each
    const int rowBase = blockIdx.y * 64;
    const int colBase = blockIdx.x * 64;

    float acc[4][4];
#pragma unroll
    for (int i = 0; i < 4; i++)
#pragma unroll
        for (int j = 0; j < 4; j++) acc[i][j] = 0.f;

    const int ar = threadIdx.x >> 2;          // 0..63 A row in tile
    const int ak = (threadIdx.x & 3) * 4;     // 0,4,8,12 k offset
    const int br = threadIdx.x >> 4;          // 0..15 B row in tile
    const int bc = (threadIdx.x & 15) * 4;    // 0..60 B col

    for (int k0 = 0; k0 < K; k0 += 16) {
        float4 av = *(const float4*)(A + (size_t)(rowBase + ar) * K + k0 + ak);
        As[ak + 0][ar] = av.x;
        As[ak + 1][ar] = av.y;
        As[ak + 2][ar] = av.z;
        As[ak + 3][ar] = av.w;
        float4 bv = *(const float4*)(B + (size_t)(k0 + br) * N + colBase + bc);
        *(float4*)&Bs[br][bc] = bv;
        __syncthreads();

#pragma unroll
        for (int kk = 0; kk < 16; kk++) {
            float a[4], b[4];
#pragma unroll
            for (int i = 0; i < 4; i++) a[i] = As[kk][ty * 4 + i];
            float4 b4 = *(const float4*)&Bs[kk][tx * 4];
            b[0] = b4.x; b[1] = b4.y; b[2] = b4.z; b[3] = b4.w;
#pragma unroll
            for (int i = 0; i < 4; i++)
#pragma unroll
                for (int j = 0; j < 4; j++) acc[i][j] += a[i] * b[j];
        }
        __syncthreads();
    }

#pragma unroll
    for (int i = 0; i < 4; i++) {
        const int row = rowBase + ty * 4 + i;
#pragma unroll
        for (int j = 0; j < 4; j++) {
            const int col = colBase + tx * 4 + j;
            float v = acc[i][j] + bias[col];
            if (GELU) {
                // quick_gelu: x * sigmoid(1.702 x)
                v = v / (1.f + expf(-1.702f * v));
            }
            C[(size_t)row * N + col] = v;
        }
    }
}

// ---------------------------------------------------------------------------
// Fused per-(batch,head) attention + residual.
// One block per (b,h); K/V head tiles in smem; one thread per query row n,
// scores kept in registers; writes fused = ctx + vis.
// ---------------------------------------------------------------------------
__global__ void __launch_bounds__(224)
attn_kernel(const float* __restrict__ q, const float* __restrict__ kbuf,
            const float* __restrict__ vbuf, const float* __restrict__ vis,
            float* __restrict__ fused)
{
    __shared__ float ks[LT * DHEAD];
    __shared__ float vs[LT * DHEAD];

    const int bh = blockIdx.x;
    const int b = bh / NHEAD;
    const int h = bh % NHEAD;

    const float* kb = kbuf + (size_t)b * LT * CI + h * DHEAD;
    const float* vb = vbuf + (size_t)b * LT * CI + h * DHEAD;
    for (int i = threadIdx.x; i < LT * DHEAD; i += blockDim.x) {
        const int l = i >> 6, d = i & 63;
        ks[i] = kb[(size_t)l * CI + d];
        vs[i] = vb[(size_t)l * CI + d];
    }
    __syncthreads();

    const int n = threadIdx.x;
    if (n >= NV) return;

    const size_t rowOff = (size_t)(b * NV + n);
    const float* qrow = q + rowOff * CI + h * DHEAD;

    float s[LT];
#pragma unroll
    for (int l = 0; l < LT; l++) s[l] = 0.f;

#pragma unroll 8
    for (int d = 0; d < DHEAD; d++) {
        const float qd = qrow[d];
#pragma unroll
        for (int l = 0; l < LT; l++) s[l] += qd * ks[l * DHEAD + d];
    }

    float mx = -1e30f;
#pragma unroll
    for (int l = 0; l < LT; l++) { s[l] *= 0.125f; mx = fmaxf(mx, s[l]); }
    float sum = 0.f;
#pragma unroll
    for (int l = 0; l < LT; l++) { s[l] = expf(s[l] - mx); sum += s[l]; }
    const float inv = 1.f / sum;
#pragma unroll
    for (int l = 0; l < LT; l++) s[l] *= inv;

    const float* visrow = vis + rowOff * CV + h * DHEAD;
    float* frow = fused + rowOff * CI + h * DHEAD;
#pragma unroll 8
    for (int d = 0; d < DHEAD; d++) {
        float acc = 0.f;
#pragma unroll
        for (int l = 0; l < LT; l++) acc += s[l] * vs[l * DHEAD + d];
        frow[d] = acc + visrow[d];
    }
}

// ---------------------------------------------------------------------------
// Head GEMV: logits[row, 0:2] = hidden[row,:] @ W2 + b2. One warp per row.
// ---------------------------------------------------------------------------
__global__ void __launch_bounds__(256)
head_kernel(const float* __restrict__ hidden, const float* __restrict__ W2,
            const float* __restrict__ b2, float* __restrict__ out)
{
    const int warp = threadIdx.x >> 5;
    const int lane = threadIdx.x & 31;
    const int row = blockIdx.x * 8 + warp;
    if (row >= MQ) return;

    const float* hr = hidden + (size_t)row * CI;
    float a0 = 0.f, a1 = 0.f;
#pragma unroll
    for (int c = lane; c < CI; c += 32) {
        const float hv = hr[c];
        a0 += hv * W2[2 * c + 0];
        a1 += hv * W2[2 * c + 1];
    }
#pragma unroll
    for (int o = 16; o > 0; o >>= 1) {
        a0 += __shfl_down_sync(0xffffffff, a0, o);
        a1 += __shfl_down_sync(0xffffffff, a1, o);
    }
    if (lane == 0) {
        out[2 * row + 0] = a0 + b2[0];
        out[2 * row + 1] = a1 + b2[1];
    }
}

// rel_BN = attn.mean(-1).mean(1): softmax rows sum to 1 -> exactly 1/32.
__global__ void relfill_kernel(float* __restrict__ rel)
{
    const int i = blockIdx.x * 256 + threadIdx.x;
    if (i < MQ) rel[i] = 0.03125f;
}

// ---------------------------------------------------------------------------
extern "C" void kernel_launch(void* const* d_in, const int* in_sizes, int n_in,
                              void* d_out, int out_size)
{
    const float* vis  = (const float*)d_in[0];
    const float* text = (const float*)d_in[1];
    const float* Wq = (const float*)d_in[2];
    const float* bq = (const float*)d_in[3];
    const float* Wk = (const float*)d_in[4];
    const float* bk = (const float*)d_in[5];
    const float* Wv = (const float*)d_in[6];
    const float* bv = (const float*)d_in[7];
    const float* W1 = (const float*)d_in[8];
    const float* b1 = (const float*)d_in[9];
    const float* W2 = (const float*)d_in[10];
    const float* b2 = (const float*)d_in[11];
    float* out = (float*)d_out;

    float *q, *k, *v, *fused, *hidden;
    cudaGetSymbolAddress((void**)&q,      g_q);
    cudaGetSymbolAddress((void**)&k,      g_k);
    cudaGetSymbolAddress((void**)&v,      g_v);
    cudaGetSymbolAddress((void**)&fused,  g_fused);
    cudaGetSymbolAddress((void**)&hidden, g_hidden);

    // K/V projections: [8192,512] @ [512,768]
    gemm_bias_kernel<false><<<dim3(CI / 64, MKV / 64), 256>>>(text, Wk, bk, k, MKV, CI, CT);
    gemm_bias_kernel<false><<<dim3(CI / 64, MKV / 64), 256>>>(text, Wv, bv, v, MKV, CI, CT);
    // Q projection: [50176,768] @ [768,768]
    gemm_bias_kernel<false><<<dim3(CI / 64, MQ / 64), 256>>>(vis, Wq, bq, q, MQ, CI, CV);
    // Attention + residual
    attn_kernel<<<BATCH * NHEAD, 224>>>(q, k, v, vis, fused);
    // MLP hidden with fused quick-gelu: [50176,768] @ [768,768]
    gemm_bias_kernel<true><<<dim3(CI / 64, MQ / 64), 256>>>(fused, W1, b1, hidden, MQ, CI, CI);
    // Head: hidden @ W2 + b2 -> logits (first MQ*2 floats of out)
    head_kernel<<<(MQ + 7) / 8, 256>>>(hidden, W2, b2, out);
    // rel_BN constant
    relfill_kernel<<<(MQ + 255) / 256, 256>>>(out + (size_t)MQ * 2);
}

// round 3
// speedup vs baseline: 2.8613x; 2.8613x over previous
#include <cuda_runtime.h>
#include <math.h>

// Problem constants
#define BATCH 256
#define NV    196
#define LT    32
#define CV    768
#define CT    512
#define CI    768
#define NHEAD 12
#define DHEAD 64

#define MQ  (BATCH*NV)   // 50176
#define MKV (BATCH*LT)   // 8192

// Scratch (allocation-free rule: __device__ globals)
__device__ float g_q[(size_t)MQ * CI];
__device__ float g_k[(size_t)MKV * CI];
__device__ float g_v[(size_t)MKV * CI];
__device__ float g_fused[(size_t)MQ * CI];
__device__ float g_hidden[(size_t)MQ * CI];

// ---------------------------------------------------------------------------
// Helpers
// ---------------------------------------------------------------------------
__device__ __forceinline__ unsigned smem_u32(const void* p) {
    return (unsigned)__cvta_generic_to_shared(p);
}
__device__ __forceinline__ void cp_async16(unsigned dst, const void* src) {
    asm volatile("cp.async.cg.shared.global [%0], [%1], 16;\n" :: "r"(dst), "l"(src));
}
__device__ __forceinline__ void cp_commit() {
    asm volatile("cp.async.commit_group;\n");
}
__device__ __forceinline__ void cp_wait0() {
    asm volatile("cp.async.wait_group 0;\n");
}
__device__ __forceinline__ void cp_wait1() {
    asm volatile("cp.async.wait_group 1;\n");
}
__device__ __forceinline__ unsigned f2tf32(float x) {
    unsigned r;
    asm("cvt.rna.tf32.f32 %0, %1;\n" : "=r"(r) : "f"(x));
    return r;
}
__device__ __forceinline__ void mma_tf32(float* c, const unsigned* a, const unsigned* b) {
    asm volatile(
        "mma.sync.aligned.m16n8k8.row.col.f32.tf32.tf32.f32 "
        "{%0,%1,%2,%3}, {%4,%5,%6,%7}, {%8,%9}, {%0,%1,%2,%3};\n"
        : "+f"(c[0]), "+f"(c[1]), "+f"(c[2]), "+f"(c[3])
        : "r"(a[0]), "r"(a[1]), "r"(a[2]), "r"(a[3]), "r"(b[0]), "r"(b[1]));
}

// ---------------------------------------------------------------------------
// TF32 tensor-core GEMM. C = A[M,K]*B[K,N] + bias (optional quick-gelu).
// Block tile 128x128, BK=16, 256 threads (8 warps 2x4), warp tile 64x32.
// Static smem (37,888 B): As[2][128][20], Bs[2][16][136]. No attribute calls.
// M%128==0, N%128==0, K%16==0 hold for all shapes used here.
// ---------------------------------------------------------------------------
#define AS_STRIDE 20
#define BS_STRIDE 136
#define AS_STAGE  (128 * AS_STRIDE)   // 2560 floats
#define BS_STAGE  (16 * BS_STRIDE)    // 2176 floats
#define BS_BASE   (2 * AS_STAGE)      // 5120

template <bool GELU>
__global__ void __launch_bounds__(256)
gemm_tf32_kernel(const float* __restrict__ A, const float* __restrict__ B,
                 const float* __restrict__ bias, float* __restrict__ C,
                 int M, int N, int K)
{
    __shared__ float sm[2 * AS_STAGE + 2 * BS_STAGE];   // 37,888 B

    const int tid = threadIdx.x;
    const int warp = tid >> 5, lane = tid & 31;
    const int g = lane >> 2, tig = lane & 3;
    const int wm = (warp >> 2) * 64;
    const int wn = (warp & 3) * 32;
    const int rowBase = blockIdx.y * 128;
    const int colBase = blockIdx.x * 128;

    float acc[4][4][4];
#pragma unroll
    for (int mt = 0; mt < 4; mt++)
#pragma unroll
        for (int nt = 0; nt < 4; nt++)
#pragma unroll
            for (int r = 0; r < 4; r++) acc[mt][nt][r] = 0.f;

    // tile load addressing (BK=16)
    const int a_row = tid >> 2;          // 0..63 (+64 second pass)
    const int a_c4  = (tid & 3) * 4;     // 0,4,8,12
    const int b_kr  = tid >> 5;          // 0..7 (+8 second pass)
    const int b_c4  = (tid & 31) * 4;    // 0..124

    const int KT = K >> 4;

    auto load_tile = [&](int kt, int s) {
        const float* Ab = A + (size_t)rowBase * K + kt * 16;
#pragma unroll
        for (int i = 0; i < 2; i++) {
            int row = i * 64 + a_row;
            cp_async16(smem_u32(&sm[s * AS_STAGE + row * AS_STRIDE + a_c4]),
                       Ab + (size_t)row * K + a_c4);
        }
        const float* Bb = B + (size_t)(kt * 16) * N + colBase;
#pragma unroll
        for (int i = 0; i < 2; i++) {
            int kr = i * 8 + b_kr;
            cp_async16(smem_u32(&sm[BS_BASE + s * BS_STAGE + kr * BS_STRIDE + b_c4]),
                       Bb + (size_t)kr * N + b_c4);
        }
    };

    load_tile(0, 0);
    cp_commit();

    for (int kt = 0; kt < KT; kt++) {
        const int buf = kt & 1;
        if (kt + 1 < KT) {
            load_tile(kt + 1, buf ^ 1);
            cp_commit();
            cp_wait1();
        } else {
            cp_wait0();
        }
        __syncthreads();

        const float* Asb = &sm[buf * AS_STAGE];
        const float* Bsb = &sm[BS_BASE + buf * BS_STAGE];

#pragma unroll
        for (int k8 = 0; k8 < 2; k8++) {
            const int kb = k8 * 8;
            unsigned a[4][4];
#pragma unroll
            for (int mt = 0; mt < 4; mt++) {
                const int m0 = wm + mt * 16 + g;
                a[mt][0] = f2tf32(Asb[m0 * AS_STRIDE + kb + tig]);
                a[mt][1] = f2tf32(Asb[(m0 + 8) * AS_STRIDE + kb + tig]);
                a[mt][2] = f2tf32(Asb[m0 * AS_STRIDE + kb + tig + 4]);
                a[mt][3] = f2tf32(Asb[(m0 + 8) * AS_STRIDE + kb + tig + 4]);
            }
            unsigned b[4][2];
#pragma unroll
            for (int nt = 0; nt < 4; nt++) {
                const int n0 = wn + nt * 8 + g;
                b[nt][0] = f2tf32(Bsb[(kb + tig) * BS_STRIDE + n0]);
                b[nt][1] = f2tf32(Bsb[(kb + tig + 4) * BS_STRIDE + n0]);
            }
#pragma unroll
            for (int mt = 0; mt < 4; mt++)
#pragma unroll
                for (int nt = 0; nt < 4; nt++)
                    mma_tf32(acc[mt][nt], a[mt], b[nt]);
        }
        __syncthreads();
    }

    // epilogue: bias (+ optional quick-gelu), float2 stores (8B aligned)
#pragma unroll
    for (int mt = 0; mt < 4; mt++) {
        const int r0 = rowBase + wm + mt * 16 + g;
        const int r1 = r0 + 8;
#pragma unroll
        for (int nt = 0; nt < 4; nt++) {
            const int c = colBase + wn + nt * 8 + tig * 2;
            const float b0 = bias[c], b1 = bias[c + 1];
            float v00 = acc[mt][nt][0] + b0, v01 = acc[mt][nt][1] + b1;
            float v10 = acc[mt][nt][2] + b0, v11 = acc[mt][nt][3] + b1;
            if (GELU) {
                v00 = v00 / (1.f + __expf(-1.702f * v00));
                v01 = v01 / (1.f + __expf(-1.702f * v01));
                v10 = v10 / (1.f + __expf(-1.702f * v10));
                v11 = v11 / (1.f + __expf(-1.702f * v11));
            }
            *(float2*)(C + (size_t)r0 * N + c) = make_float2(v00, v01);
            *(float2*)(C + (size_t)r1 * N + c) = make_float2(v10, v11);
        }
    }
}

// ---------------------------------------------------------------------------
// Fused attention + residual. One block per (b, h, query-chunk).
// 2 chunks of 98 queries -> static smem 42.7 KB (ks 8K, vs 8K, qs 26.7K).
// ---------------------------------------------------------------------------
#define QCHUNK 98
#define QS_STRIDE 68

__global__ void __launch_bounds__(128)
attn_kernel(const float* __restrict__ q, const float* __restrict__ kbuf,
            const float* __restrict__ vbuf, const float* __restrict__ vis,
            float* __restrict__ fused)
{
    __shared__ float ks[LT * DHEAD];          // 2048 floats
    __shared__ float vs[LT * DHEAD];          // 2048 floats
    __shared__ float qs[QCHUNK * QS_STRIDE];  // 6664 floats

    const int bh = blockIdx.x >> 1;
    const int chunk = blockIdx.x & 1;
    const int b = bh / NHEAD;
    const int h = bh % NHEAD;
    const int tid = threadIdx.x;
    const int nBase = chunk * QCHUNK;

    const float* kb = kbuf + (size_t)b * LT * CI + h * DHEAD;
    const float* vb = vbuf + (size_t)b * LT * CI + h * DHEAD;
    for (int f = tid; f < 512; f += 128) {
        const int l = f >> 4, d4 = f & 15;
        ((float4*)ks)[l * 16 + d4] = *(const float4*)(kb + (size_t)l * CI + d4 * 4);
        ((float4*)vs)[l * 16 + d4] = *(const float4*)(vb + (size_t)l * CI + d4 * 4);
    }
    const float* qb = q + ((size_t)b * NV + nBase) * CI + h * DHEAD;
    for (int f = tid; f < QCHUNK * 16; f += 128) {
        const int n = f >> 4, d4 = f & 15;
        *(float4*)(qs + n * QS_STRIDE + d4 * 4) =
            *(const float4*)(qb + (size_t)n * CI + d4 * 4);
    }
    __syncthreads();

    const int n = tid;
    if (n >= QCHUNK) return;

    float s[LT];
#pragma unroll
    for (int l = 0; l < LT; l++) s[l] = 0.f;

#pragma unroll
    for (int d4 = 0; d4 < 16; d4++) {
        const float4 q4 = *(const float4*)(qs + n * QS_STRIDE + d4 * 4);
#pragma unroll
        for (int l = 0; l < LT; l++) {
            const float4 k4 = ((const float4*)ks)[l * 16 + d4];
            s[l] += q4.x * k4.x + q4.y * k4.y + q4.z * k4.z + q4.w * k4.w;
        }
    }

    float mx = -1e30f;
#pragma unroll
    for (int l = 0; l < LT; l++) { s[l] *= 0.125f; mx = fmaxf(mx, s[l]); }
    float sum = 0.f;
#pragma unroll
    for (int l = 0; l < LT; l++) { s[l] = __expf(s[l] - mx); sum += s[l]; }
    const float inv = 1.f / sum;
#pragma unroll
    for (int l = 0; l < LT; l++) s[l] *= inv;

    const size_t rowOff = (size_t)b * NV + nBase + n;
    const float* visrow = vis + rowOff * CV + h * DHEAD;
    float* frow = fused + rowOff * CI + h * DHEAD;

#pragma unroll
    for (int d4 = 0; d4 < 16; d4++) {
        float4 acc = make_float4(0.f, 0.f, 0.f, 0.f);
#pragma unroll
        for (int l = 0; l < LT; l++) {
            const float4 v4 = ((const float4*)vs)[l * 16 + d4];
            acc.x += s[l] * v4.x; acc.y += s[l] * v4.y;
            acc.z += s[l] * v4.z; acc.w += s[l] * v4.w;
        }
        const float4 r4 = *(const float4*)(visrow + d4 * 4);
        acc.x += r4.x; acc.y += r4.y; acc.z += r4.z; acc.w += r4.w;
        *(float4*)(frow + d4 * 4) = acc;
    }
}

// ---------------------------------------------------------------------------
// Head GEMV: logits[row, 0:2] = hidden[row,:] @ W2 + b2. One warp per row.
// ---------------------------------------------------------------------------
__global__ void __launch_bounds__(256)
head_kernel(const float* __restrict__ hidden, const float* __restrict__ W2,
            const float* __restrict__ b2, float* __restrict__ out)
{
    const int warp = threadIdx.x >> 5;
    const int lane = threadIdx.x & 31;
    const int row = blockIdx.x * 8 + warp;
    if (row >= MQ) return;

    const float* hr = hidden + (size_t)row * CI;
    float a0 = 0.f, a1 = 0.f;
#pragma unroll
    for (int c = lane; c < CI; c += 32) {
        const float hv = hr[c];
        a0 += hv * W2[2 * c + 0];
        a1 += hv * W2[2 * c + 1];
    }
#pragma unroll
    for (int o = 16; o > 0; o >>= 1) {
        a0 += __shfl_down_sync(0xffffffff, a0, o);
        a1 += __shfl_down_sync(0xffffffff, a1, o);
    }
    if (lane == 0) {
        out[2 * row + 0] = a0 + b2[0];
        out[2 * row + 1] = a1 + b2[1];
    }
}

// rel_BN = attn.mean(-1).mean(1): softmax rows sum to 1 -> exactly 1/32.
__global__ void relfill_kernel(float* __restrict__ rel)
{
    const int i = blockIdx.x * 256 + threadIdx.x;
    if (i < MQ) rel[i] = 0.03125f;
}

// ---------------------------------------------------------------------------
extern "C" void kernel_launch(void* const* d_in, const int* in_sizes, int n_in,
                              void* d_out, int out_size)
{
    const float* vis  = (const float*)d_in[0];
    const float* text = (const float*)d_in[1];
    const float* Wq = (const float*)d_in[2];
    const float* bq = (const float*)d_in[3];
    const float* Wk = (const float*)d_in[4];
    const float* bk = (const float*)d_in[5];
    const float* Wv = (const float*)d_in[6];
    const float* bv = (const float*)d_in[7];
    const float* W1 = (const float*)d_in[8];
    const float* b1 = (const float*)d_in[9];
    const float* W2 = (const float*)d_in[10];
    const float* b2 = (const float*)d_in[11];
    float* out = (float*)d_out;

    float *q, *k, *v, *fused, *hidden;
    cudaGetSymbolAddress((void**)&q,      g_q);
    cudaGetSymbolAddress((void**)&k,      g_k);
    cudaGetSymbolAddress((void**)&v,      g_v);
    cudaGetSymbolAddress((void**)&fused,  g_fused);
    cudaGetSymbolAddress((void**)&hidden, g_hidden);

    // K/V projections: [8192,512] @ [512,768]
    gemm_tf32_kernel<false><<<dim3(CI / 128, MKV / 128), 256>>>(text, Wk, bk, k, MKV, CI, CT);
    gemm_tf32_kernel<false><<<dim3(CI / 128, MKV / 128), 256>>>(text, Wv, bv, v, MKV, CI, CT);
    // Q projection: [50176,768] @ [768,768]
    gemm_tf32_kernel<false><<<dim3(CI / 128, MQ / 128), 256>>>(vis, Wq, bq, q, MQ, CI, CV);
    // Attention + residual (2 query chunks per (b,h))
    attn_kernel<<<BATCH * NHEAD * 2, 128>>>(q, k, v, vis, fused);
    // MLP hidden with fused quick-gelu: [50176,768] @ [768,768]
    gemm_tf32_kernel<true><<<dim3(CI / 128, MQ / 128), 256>>>(fused, W1, b1, hidden, MQ, CI, CI);
    // Head GEMV
    head_kernel<<<(MQ + 7) / 8, 256>>>(hidden, W2, b2, out);
    // rel_BN constant
    relfill_kernel<<<(MQ + 255) / 256, 256>>>(out + (size_t)MQ * 2);
}

// round 5
// speedup vs baseline: 2.9899x; 1.0449x over previous
#include <cuda_runtime.h>
#include <cstdint>
#include <math.h>

// Problem constants
#define BATCH 256
#define NV    196
#define LT    32
#define CV    768
#define CT    512
#define CI    768
#define NHEAD 12
#define DHEAD 64

#define MQ  (BATCH*NV)   // 50176
#define MKV (BATCH*LT)   // 8192

// Scratch (allocation-free rule: __device__ globals)
__device__ float g_q[(size_t)MQ * CI];
__device__ float g_k[(size_t)MKV * CI];
__device__ float g_v[(size_t)MKV * CI];
__device__ float g_fused[(size_t)MQ * CI];
__device__ float g_hidden[(size_t)MQ * CI];
// tf32-pre-rounded weights (same [K,N] layout as inputs)
__device__ float g_wqR[(size_t)CV * CI];
__device__ float g_wkR[(size_t)CT * CI];
__device__ float g_wvR[(size_t)CT * CI];
__device__ float g_w1R[(size_t)CI * CI];

// ---------------------------------------------------------------------------
// Helpers
// ---------------------------------------------------------------------------
__device__ __forceinline__ unsigned f2tf32(float x) {
    unsigned r;
    asm("cvt.rna.tf32.f32 %0, %1;\n" : "=r"(r) : "f"(x));
    return r;
}
__device__ __forceinline__ float tf32r(float x) { return __uint_as_float(f2tf32(x)); }

__device__ __forceinline__ void mma_tf32(float* c, const unsigned* a, const unsigned* b) {
    asm volatile(
        "mma.sync.aligned.m16n8k8.row.col.f32.tf32.tf32.f32 "
        "{%0,%1,%2,%3}, {%4,%5,%6,%7}, {%8,%9}, {%0,%1,%2,%3};\n"
        : "+f"(c[0]), "+f"(c[1]), "+f"(c[2]), "+f"(c[3])
        : "r"(a[0]), "r"(a[1]), "r"(a[2]), "r"(a[3]), "r"(b[0]), "r"(b[1]));
}

// ---------------------------------------------------------------------------
// Elementwise tf32 round for weights (keeps [K,N] layout).
// ---------------------------------------------------------------------------
__global__ void __launch_bounds__(256)
round_tf32_kernel(const float* __restrict__ in, float* __restrict__ out, int n4)
{
    const int i = blockIdx.x * 256 + threadIdx.x;
    if (i < n4) {
        float4 v = ((const float4*)in)[i];
        v.x = tf32r(v.x); v.y = tf32r(v.y); v.z = tf32r(v.z); v.w = tf32r(v.w);
        ((float4*)out)[i] = v;
    }
}

// ---------------------------------------------------------------------------
// TF32 mma.sync GEMM. C = A[M,K]*B[K,N] + bias (optional quick-gelu).
// Block tile 128x128, BK=32, 256 threads (8 warps 2x4), warp tile 64x32.
// Single smem buffer + register staging (LDG next tile overlapped with MMA).
// A is tf32-rounded at STS; B (weights) pre-rounded globally -> inner loop is
// pure LDS + HMMA. M%128==0, N%128==0, K%32==0 hold for all shapes here.
// Smem: As[128][36] + Bs[32][136] = 35,840 B (static, <48KB).
// ---------------------------------------------------------------------------
#define AS_STRIDE 36
#define BS_STRIDE 136
#define AS_FLOATS (128 * AS_STRIDE)   // 4608
#define BS_FLOATS (32 * BS_STRIDE)    // 4352

template <bool GELU>
__global__ void __launch_bounds__(256)
gemm_tf32_kernel(const float* __restrict__ A, const float* __restrict__ B,
                 const float* __restrict__ bias, float* __restrict__ C,
                 int M, int N, int K)
{
    __shared__ float sm[AS_FLOATS + BS_FLOATS];
    float* As = sm;
    float* Bs = sm + AS_FLOATS;

    const int tid = threadIdx.x;
    const int warp = tid >> 5, lane = tid & 31;
    const int g = lane >> 2, tig = lane & 3;
    const int wm = (warp >> 2) * 64;
    const int wn = (warp & 3) * 32;
    const int rowBase = blockIdx.y * 128;
    const int colBase = blockIdx.x * 128;

    float acc[4][4][4];
#pragma unroll
    for (int mt = 0; mt < 4; mt++)
#pragma unroll
        for (int nt = 0; nt < 4; nt++)
#pragma unroll
            for (int r = 0; r < 4; r++) acc[mt][nt][r] = 0.f;

    const int KT = K >> 5;
    float4 ar[4], br[4];

    // A: 128 rows x 32 cols = 1024 float4; B: 32 rows x 128 cols = 1024 float4.
    auto ldg_tiles = [&](int kt) {
        const float* Ab = A + (size_t)rowBase * K + kt * 32;
#pragma unroll
        for (int i = 0; i < 4; i++) {
            const int f = tid + i * 256;
            const int r = f >> 3, c4 = (f & 7) * 4;
            ar[i] = *(const float4*)(Ab + (size_t)r * K + c4);
        }
        const float* Bb = B + (size_t)(kt * 32) * N + colBase;
#pragma unroll
        for (int i = 0; i < 4; i++) {
            const int f = tid + i * 256;
            const int kr = f >> 5, c4 = (f & 31) * 4;
            br[i] = *(const float4*)(Bb + (size_t)kr * N + c4);
        }
    };

    ldg_tiles(0);

    for (int kt = 0; kt < KT; kt++) {
        if (kt) __syncthreads();
        // stage regs -> smem (A rounded to tf32 here; B already rounded)
#pragma unroll
        for (int i = 0; i < 4; i++) {
            const int f = tid + i * 256;
            const int r = f >> 3, c4 = (f & 7) * 4;
            float4 v = ar[i];
            v.x = tf32r(v.x); v.y = tf32r(v.y); v.z = tf32r(v.z); v.w = tf32r(v.w);
            *(float4*)(As + r * AS_STRIDE + c4) = v;
        }
#pragma unroll
        for (int i = 0; i < 4; i++) {
            const int f = tid + i * 256;
            const int kr = f >> 5, c4 = (f & 31) * 4;
            *(float4*)(Bs + kr * BS_STRIDE + c4) = br[i];
        }
        __syncthreads();

        if (kt + 1 < KT) ldg_tiles(kt + 1);   // overlap with MMA below

#pragma unroll
        for (int k8 = 0; k8 < 4; k8++) {
            const int kb = k8 * 8;
            unsigned a[4][4];
#pragma unroll
            for (int mt = 0; mt < 4; mt++) {
                const int m0 = wm + mt * 16 + g;
                a[mt][0] = __float_as_uint(As[m0 * AS_STRIDE + kb + tig]);
                a[mt][1] = __float_as_uint(As[(m0 + 8) * AS_STRIDE + kb + tig]);
                a[mt][2] = __float_as_uint(As[m0 * AS_STRIDE + kb + tig + 4]);
                a[mt][3] = __float_as_uint(As[(m0 + 8) * AS_STRIDE + kb + tig + 4]);
            }
            unsigned b[4][2];
#pragma unroll
            for (int nt = 0; nt < 4; nt++) {
                const int n0 = wn + nt * 8 + g;
                b[nt][0] = __float_as_uint(Bs[(kb + tig) * BS_STRIDE + n0]);
                b[nt][1] = __float_as_uint(Bs[(kb + tig + 4) * BS_STRIDE + n0]);
            }
#pragma unroll
            for (int mt = 0; mt < 4; mt++)
#pragma unroll
                for (int nt = 0; nt < 4; nt++)
                    mma_tf32(acc[mt][nt], a[mt], b[nt]);
        }
    }

    // epilogue: bias (+ optional quick-gelu), float2 stores
#pragma unroll
    for (int mt = 0; mt < 4; mt++) {
        const int r0 = rowBase + wm + mt * 16 + g;
        const int r1 = r0 + 8;
#pragma unroll
        for (int nt = 0; nt < 4; nt++) {
            const int c = colBase + wn + nt * 8 + tig * 2;
            const float b0 = bias[c], b1 = bias[c + 1];
            float v00 = acc[mt][nt][0] + b0, v01 = acc[mt][nt][1] + b1;
            float v10 = acc[mt][nt][2] + b0, v11 = acc[mt][nt][3] + b1;
            if (GELU) {
                v00 = v00 / (1.f + __expf(-1.702f * v00));
                v01 = v01 / (1.f + __expf(-1.702f * v01));
                v10 = v10 / (1.f + __expf(-1.702f * v10));
                v11 = v11 / (1.f + __expf(-1.702f * v11));
            }
            *(float2*)(C + (size_t)r0 * N + c) = make_float2(v00, v01);
            *(float2*)(C + (size_t)r1 * N + c) = make_float2(v10, v11);
        }
    }
}

// ---------------------------------------------------------------------------
// Fused attention + residual. 2 threads per query (each owns 32 of D=64),
// one shfl_xor(1) combines score partials. Block 224 threads = 98 queries,
// 2 chunks per (b,h). All lanes stay active (clamped) so shfl is safe;
// stores are guarded.
// ---------------------------------------------------------------------------
__global__ void __launch_bounds__(224)
attn_kernel(const float* __restrict__ q, const float* __restrict__ kbuf,
            const float* __restrict__ vbuf, const float* __restrict__ vis,
            float* __restrict__ fused)
{
    __shared__ float ks[LT * DHEAD];   // 2048 floats
    __shared__ float vs[LT * DHEAD];   // 2048 floats

    const int bh = blockIdx.x >> 1;
    const int chunk = blockIdx.x & 1;
    const int b = bh / NHEAD;
    const int h = bh % NHEAD;
    const int tid = threadIdx.x;

    const float* kb = kbuf + (size_t)b * LT * CI + h * DHEAD;
    const float* vb = vbuf + (size_t)b * LT * CI + h * DHEAD;
    for (int f = tid; f < 512; f += 224) {
        const int l = f >> 4, d4 = f & 15;
        ((float4*)ks)[l * 16 + d4] = *(const float4*)(kb + (size_t)l * CI + d4 * 4);
        ((float4*)vs)[l * 16 + d4] = *(const float4*)(vb + (size_t)l * CI + d4 * 4);
    }
    __syncthreads();

    const bool active = tid < 196;
    const int qi = active ? (tid >> 1) : 97;        // clamp keeps lanes alive
    const int half = (tid & 1) * 32;
    const int n = chunk * 98 + qi;
    const size_t rowOff = (size_t)b * NV + n;

    // load this thread's 32 q values
    const float* qrow = q + rowOff * CI + h * DHEAD + half;
    float4 q4[8];
#pragma unroll
    for (int i = 0; i < 8; i++) q4[i] = *(const float4*)(qrow + i * 4);

    float s[LT];
#pragma unroll
    for (int l = 0; l < LT; l++) s[l] = 0.f;

#pragma unroll
    for (int i = 0; i < 8; i++) {
#pragma unroll
        for (int l = 0; l < LT; l++) {
            const float4 k4 = *(const float4*)(ks + l * DHEAD + half + i * 4);
            s[l] += q4[i].x * k4.x + q4[i].y * k4.y + q4[i].z * k4.z + q4[i].w * k4.w;
        }
    }
#pragma unroll
    for (int l = 0; l < LT; l++)
        s[l] += __shfl_xor_sync(0xffffffff, s[l], 1);

    float mx = -1e30f;
#pragma unroll
    for (int l = 0; l < LT; l++) { s[l] *= 0.125f; mx = fmaxf(mx, s[l]); }
    float sum = 0.f;
#pragma unroll
    for (int l = 0; l < LT; l++) { s[l] = __expf(s[l] - mx); sum += s[l]; }
    const float inv = 1.f / sum;
#pragma unroll
    for (int l = 0; l < LT; l++) s[l] *= inv;

    const float* visrow = vis + rowOff * CV + h * DHEAD + half;
    float* frow = fused + rowOff * CI + h * DHEAD + half;
#pragma unroll
    for (int i = 0; i < 8; i++) {
        float4 acc = make_float4(0.f, 0.f, 0.f, 0.f);
#pragma unroll
        for (int l = 0; l < LT; l++) {
            const float4 v4 = *(const float4*)(vs + l * DHEAD + half + i * 4);
            acc.x += s[l] * v4.x; acc.y += s[l] * v4.y;
            acc.z += s[l] * v4.z; acc.w += s[l] * v4.w;
        }
        const float4 r4 = *(const float4*)(visrow + i * 4);
        acc.x += r4.x; acc.y += r4.y; acc.z += r4.z; acc.w += r4.w;
        if (active) *(float4*)(frow + i * 4) = acc;
    }
}

// ---------------------------------------------------------------------------
// Head GEMV: logits[row, 0:2] = hidden[row,:] @ W2 + b2. One warp per row.
// ---------------------------------------------------------------------------
__global__ void __launch_bounds__(256)
head_kernel(const float* __restrict__ hidden, const float* __restrict__ W2,
            const float* __restrict__ b2, float* __restrict__ out)
{
    const int warp = threadIdx.x >> 5;
    const int lane = threadIdx.x & 31;
    const int row = blockIdx.x * 8 + warp;
    if (row >= MQ) return;

    const float* hr = hidden + (size_t)row * CI;
    float a0 = 0.f, a1 = 0.f;
#pragma unroll
    for (int c = lane; c < CI; c += 32) {
        const float hv = hr[c];
        a0 += hv * W2[2 * c + 0];
        a1 += hv * W2[2 * c + 1];
    }
#pragma unroll
    for (int o = 16; o > 0; o >>= 1) {
        a0 += __shfl_down_sync(0xffffffff, a0, o);
        a1 += __shfl_down_sync(0xffffffff, a1, o);
    }
    if (lane == 0) {
        out[2 * row + 0] = a0 + b2[0];
        out[2 * row + 1] = a1 + b2[1];
    }
}

// rel_BN = attn.mean(-1).mean(1): softmax rows sum to 1 -> exactly 1/32.
__global__ void relfill_kernel(float* __restrict__ rel)
{
    const int i = blockIdx.x * 256 + threadIdx.x;
    if (i < MQ) rel[i] = 0.03125f;
}

// ---------------------------------------------------------------------------
extern "C" void kernel_launch(void* const* d_in, const int* in_sizes, int n_in,
                              void* d_out, int out_size)
{
    const float* vis  = (const float*)d_in[0];
    const float* text = (const float*)d_in[1];
    const float* Wq = (const float*)d_in[2];
    const float* bq = (const float*)d_in[3];
    const float* Wk = (const float*)d_in[4];
    const float* bk = (const float*)d_in[5];
    const float* Wv = (const float*)d_in[6];
    const float* bv = (const float*)d_in[7];
    const float* W1 = (const float*)d_in[8];
    const float* b1 = (const float*)d_in[9];
    const float* W2 = (const float*)d_in[10];
    const float* b2 = (const float*)d_in[11];
    float* out = (float*)d_out;

    float *q, *k, *v, *fused, *hidden, *wqR, *wkR, *wvR, *w1R;
    cudaGetSymbolAddress((void**)&q,      g_q);
    cudaGetSymbolAddress((void**)&k,      g_k);
    cudaGetSymbolAddress((void**)&v,      g_v);
    cudaGetSymbolAddress((void**)&fused,  g_fused);
    cudaGetSymbolAddress((void**)&hidden, g_hidden);
    cudaGetSymbolAddress((void**)&wqR,    g_wqR);
    cudaGetSymbolAddress((void**)&wkR,    g_wkR);
    cudaGetSymbolAddress((void**)&wvR,    g_wvR);
    cudaGetSymbolAddress((void**)&w1R,    g_w1R);

    // Pre-round weights to tf32 (removes all cvt from GEMM inner loops)
    round_tf32_kernel<<<(CT * CI / 4 + 255) / 256, 256>>>(Wk, wkR, CT * CI / 4);
    round_tf32_kernel<<<(CT * CI / 4 + 255) / 256, 256>>>(Wv, wvR, CT * CI / 4);
    round_tf32_kernel<<<(CV * CI / 4 + 255) / 256, 256>>>(Wq, wqR, CV * CI / 4);
    round_tf32_kernel<<<(CI * CI / 4 + 255) / 256, 256>>>(W1, w1R, CI * CI / 4);

    // K/V projections: [8192,512] @ [512,768]
    gemm_tf32_kernel<false><<<dim3(CI / 128, MKV / 128), 256>>>(text, wkR, bk, k, MKV, CI, CT);
    gemm_tf32_kernel<false><<<dim3(CI / 128, MKV / 128), 256>>>(text, wvR, bv, v, MKV, CI, CT);
    // Q projection: [50176,768] @ [768,768]
    gemm_tf32_kernel<false><<<dim3(CI / 128, MQ / 128), 256>>>(vis, wqR, bq, q, MQ, CI, CV);
    // Attention + residual
    attn_kernel<<<BATCH * NHEAD * 2, 224>>>(q, k, v, vis, fused);
    // MLP hidden with fused quick-gelu: [50176,768] @ [768,768]
    gemm_tf32_kernel<true><<<dim3(CI / 128, MQ / 128), 256>>>(fused, w1R, b1, hidden, MQ, CI, CI);
    // Head GEMV
    head_kernel<<<(MQ + 7) / 8, 256>>>(hidden, W2, b2, out);
    // rel_BN constant
    relfill_kernel<<<(MQ + 255) / 256, 256>>>(out + (size_t)MQ * 2);
}

// round 6
// speedup vs baseline: 4.0046x; 1.3394x over previous
#include <cuda_runtime.h>
#include <cuda_fp16.h>
#include <cstdint>
#include <math.h>

// Problem constants
#define BATCH 256
#define NV    196
#define LT    32
#define CV    768
#define CT    512
#define CI    768
#define NHEAD 12
#define DHEAD 64

#define MQ  (BATCH*NV)   // 50176
#define MKV (BATCH*LT)   // 8192
#define NKV 1536         // combined K|V projection width

// Scratch (allocation-free rule: __device__ globals)
__device__ float g_q[(size_t)MQ * CI];
__device__ float g_kv[(size_t)MKV * NKV];
__device__ float g_fused[(size_t)MQ * CI];
__device__ float g_hidden[(size_t)MQ * CI];
// fp16 packed weights, k-pair-major: wp[k2][n] = (W[2k2][n], W[2k2+1][n])
__device__ __half2 g_wkvP[(size_t)(CT/2) * NKV];
__device__ __half2 g_wqP[(size_t)(CV/2) * CI];
__device__ __half2 g_w1P[(size_t)(CI/2) * CI];
__device__ float   g_bkv[NKV];

// ---------------------------------------------------------------------------
__device__ __forceinline__ void mma_f16(float* c, const unsigned* a, const unsigned* b) {
    asm volatile(
        "mma.sync.aligned.m16n8k16.row.col.f32.f16.f16.f32 "
        "{%0,%1,%2,%3}, {%4,%5,%6,%7}, {%8,%9}, {%0,%1,%2,%3};\n"
        : "+f"(c[0]), "+f"(c[1]), "+f"(c[2]), "+f"(c[3])
        : "r"(a[0]), "r"(a[1]), "r"(a[2]), "r"(a[3]), "r"(b[0]), "r"(b[1]));
}

// ---------------------------------------------------------------------------
// Pack fp32 weights [K,N] -> half2 k-pair-major [K/2][outN] at column colOff.
// ---------------------------------------------------------------------------
__global__ void __launch_bounds__(256)
pack_w_kernel(const float* __restrict__ W, __half2* __restrict__ out,
              int K, int N, int outN, int colOff)
{
    const int idx = blockIdx.x * 256 + threadIdx.x;
    const int total = (K / 2) * N;
    if (idx >= total) return;
    const int k2 = idx / N, n = idx % N;
    out[(size_t)k2 * outN + colOff + n] =
        __floats2half2_rn(W[(size_t)(2 * k2) * N + n], W[(size_t)(2 * k2 + 1) * N + n]);
}

// ---------------------------------------------------------------------------
// FP16 mma.sync GEMM. C = A[M,K](fp32) * Bp(k-pair half2 [K/2][N]) + bias.
// Block 128x128, BK=32, 256 threads (8 warps 2x4), warp tile 64x32.
// Single smem buffer + register staging. A converted fp32->half2 at STS.
// Smem: As 128x20 half2 (10240B) + Bs 16x136 half2 (8704B) = 18,944B.
// M%128==0, N%128==0, K%32==0 hold for all shapes used here.
// ---------------------------------------------------------------------------
#define AS2_STRIDE 20
#define BS2_STRIDE 136

template <bool GELU>
__global__ void __launch_bounds__(256)
gemm_f16_kernel(const float* __restrict__ A, const __half2* __restrict__ Bp,
                const float* __restrict__ bias, float* __restrict__ C,
                int M, int N, int K)
{
    __shared__ __half2 As[128 * AS2_STRIDE];
    __shared__ __half2 Bs[16 * BS2_STRIDE];

    const int tid = threadIdx.x;
    const int warp = tid >> 5, lane = tid & 31;
    const int g = lane >> 2, tig = lane & 3;
    const int wm = (warp >> 2) * 64;
    const int wn = (warp & 3) * 32;
    const int rowBase = blockIdx.y * 128;
    const int colBase = blockIdx.x * 128;

    float acc[4][4][4];
#pragma unroll
    for (int mt = 0; mt < 4; mt++)
#pragma unroll
        for (int nt = 0; nt < 4; nt++)
#pragma unroll
            for (int r = 0; r < 4; r++) acc[mt][nt][r] = 0.f;

    const int KT = K >> 5;
    float4 ar[4], br[2];

    // A tile: 128 rows x 32 fp32 = 1024 float4 (4/thread).
    // B tile: 16 k2-rows x 128 half2 = 512 float4 (2/thread).
    auto ldg_tiles = [&](int kt) {
        const float* Ab = A + (size_t)rowBase * K + kt * 32;
#pragma unroll
        for (int i = 0; i < 4; i++) {
            const int f = tid + i * 256;
            const int r = f >> 3, c4 = (f & 7) * 4;
            ar[i] = *(const float4*)(Ab + (size_t)r * K + c4);
        }
        const __half2* Bb = Bp + (size_t)(kt * 16) * N + colBase;
#pragma unroll
        for (int i = 0; i < 2; i++) {
            const int f = tid + i * 256;
            const int k2 = f >> 5, n4 = (f & 31) * 4;
            br[i] = *(const float4*)(Bb + (size_t)k2 * N + n4);
        }
    };

    ldg_tiles(0);

    for (int kt = 0; kt < KT; kt++) {
        if (kt) __syncthreads();
#pragma unroll
        for (int i = 0; i < 4; i++) {
            const int f = tid + i * 256;
            const int r = f >> 3, c2 = (f & 7) * 2;   // half2 col 0..14
            const __half2 h0 = __floats2half2_rn(ar[i].x, ar[i].y);
            const __half2 h1 = __floats2half2_rn(ar[i].z, ar[i].w);
            __half2* dst = &As[r * AS2_STRIDE + c2];
            dst[0] = h0; dst[1] = h1;
        }
#pragma unroll
        for (int i = 0; i < 2; i++) {
            const int f = tid + i * 256;
            const int k2 = f >> 5, n4 = (f & 31) * 4;
            *(float4*)&Bs[k2 * BS2_STRIDE + n4] = br[i];
        }
        __syncthreads();

        if (kt + 1 < KT) ldg_tiles(kt + 1);   // overlap with MMA below

#pragma unroll
        for (int k16 = 0; k16 < 2; k16++) {
            const int kb2 = k16 * 8;
            unsigned a[4][4];
#pragma unroll
            for (int mt = 0; mt < 4; mt++) {
                const int m0 = wm + mt * 16 + g;
                a[mt][0] = *(const unsigned*)&As[m0 * AS2_STRIDE + kb2 + tig];
                a[mt][1] = *(const unsigned*)&As[(m0 + 8) * AS2_STRIDE + kb2 + tig];
                a[mt][2] = *(const unsigned*)&As[m0 * AS2_STRIDE + kb2 + 4 + tig];
                a[mt][3] = *(const unsigned*)&As[(m0 + 8) * AS2_STRIDE + kb2 + 4 + tig];
            }
            unsigned b[4][2];
#pragma unroll
            for (int nt = 0; nt < 4; nt++) {
                const int n0 = wn + nt * 8 + g;
                b[nt][0] = *(const unsigned*)&Bs[(kb2 + tig) * BS2_STRIDE + n0];
                b[nt][1] = *(const unsigned*)&Bs[(kb2 + 4 + tig) * BS2_STRIDE + n0];
            }
#pragma unroll
            for (int mt = 0; mt < 4; mt++)
#pragma unroll
                for (int nt = 0; nt < 4; nt++)
                    mma_f16(acc[mt][nt], a[mt], b[nt]);
        }
    }

    // epilogue: bias (+ optional quick-gelu), float2 stores
#pragma unroll
    for (int mt = 0; mt < 4; mt++) {
        const int r0 = rowBase + wm + mt * 16 + g;
        const int r1 = r0 + 8;
#pragma unroll
        for (int nt = 0; nt < 4; nt++) {
            const int c = colBase + wn + nt * 8 + tig * 2;
            const float b0 = bias[c], b1 = bias[c + 1];
            float v00 = acc[mt][nt][0] + b0, v01 = acc[mt][nt][1] + b1;
            float v10 = acc[mt][nt][2] + b0, v11 = acc[mt][nt][3] + b1;
            if (GELU) {
                v00 = v00 / (1.f + __expf(-1.702f * v00));
                v01 = v01 / (1.f + __expf(-1.702f * v01));
                v10 = v10 / (1.f + __expf(-1.702f * v10));
                v11 = v11 / (1.f + __expf(-1.702f * v11));
            }
            *(float2*)(C + (size_t)r0 * N + c) = make_float2(v00, v01);
            *(float2*)(C + (size_t)r1 * N + c) = make_float2(v10, v11);
        }
    }
}

// ---------------------------------------------------------------------------
// Fused attention + residual. 2 threads per query (each owns 32 of D=64).
// kvbuf is the combined [MKV][1536] projection: K at h*64, V at 768 + h*64.
// ---------------------------------------------------------------------------
__global__ void __launch_bounds__(224)
attn_kernel(const float* __restrict__ q, const float* __restrict__ kvbuf,
            const float* __restrict__ vis, float* __restrict__ fused)
{
    __shared__ float ks[LT * DHEAD];
    __shared__ float vs[LT * DHEAD];

    const int bh = blockIdx.x >> 1;
    const int chunk = blockIdx.x & 1;
    const int b = bh / NHEAD;
    const int h = bh % NHEAD;
    const int tid = threadIdx.x;

    const float* kb = kvbuf + (size_t)b * LT * NKV + h * DHEAD;
    const float* vb = kb + 768;
    for (int f = tid; f < 512; f += 224) {
        const int l = f >> 4, d4 = f & 15;
        ((float4*)ks)[l * 16 + d4] = *(const float4*)(kb + (size_t)l * NKV + d4 * 4);
        ((float4*)vs)[l * 16 + d4] = *(const float4*)(vb + (size_t)l * NKV + d4 * 4);
    }
    __syncthreads();

    const bool active = tid < 196;
    const int qi = active ? (tid >> 1) : 97;
    const int half = (tid & 1) * 32;
    const int n = chunk * 98 + qi;
    const size_t rowOff = (size_t)b * NV + n;

    const float* qrow = q + rowOff * CI + h * DHEAD + half;
    float4 q4[8];
#pragma unroll
    for (int i = 0; i < 8; i++) q4[i] = *(const float4*)(qrow + i * 4);

    float s[LT];
#pragma unroll
    for (int l = 0; l < LT; l++) s[l] = 0.f;

#pragma unroll
    for (int i = 0; i < 8; i++) {
#pragma unroll
        for (int l = 0; l < LT; l++) {
            const float4 k4 = *(const float4*)(ks + l * DHEAD + half + i * 4);
            s[l] += q4[i].x * k4.x + q4[i].y * k4.y + q4[i].z * k4.z + q4[i].w * k4.w;
        }
    }
#pragma unroll
    for (int l = 0; l < LT; l++)
        s[l] += __shfl_xor_sync(0xffffffff, s[l], 1);

    float mx = -1e30f;
#pragma unroll
    for (int l = 0; l < LT; l++) { s[l] *= 0.125f; mx = fmaxf(mx, s[l]); }
    float sum = 0.f;
#pragma unroll
    for (int l = 0; l < LT; l++) { s[l] = __expf(s[l] - mx); sum += s[l]; }
    const float inv = 1.f / sum;
#pragma unroll
    for (int l = 0; l < LT; l++) s[l] *= inv;

    const float* visrow = vis + rowOff * CV + h * DHEAD + half;
    float* frow = fused + rowOff * CI + h * DHEAD + half;
#pragma unroll
    for (int i = 0; i < 8; i++) {
        float4 acc = make_float4(0.f, 0.f, 0.f, 0.f);
#pragma unroll
        for (int l = 0; l < LT; l++) {
            const float4 v4 = *(const float4*)(vs + l * DHEAD + half + i * 4);
            acc.x += s[l] * v4.x; acc.y += s[l] * v4.y;
            acc.z += s[l] * v4.z; acc.w += s[l] * v4.w;
        }
        const float4 r4 = *(const float4*)(visrow + i * 4);
        acc.x += r4.x; acc.y += r4.y; acc.z += r4.z; acc.w += r4.w;
        if (active) *(float4*)(frow + i * 4) = acc;
    }
}

// ---------------------------------------------------------------------------
// Head GEMV: logits[row, 0:2] = hidden[row,:] @ W2 + b2. One warp per row.
// ---------------------------------------------------------------------------
__global__ void __launch_bounds__(256)
head_kernel(const float* __restrict__ hidden, const float* __restrict__ W2,
            const float* __restrict__ b2, float* __restrict__ out)
{
    const int warp = threadIdx.x >> 5;
    const int lane = threadIdx.x & 31;
    const int row = blockIdx.x * 8 + warp;
    if (row >= MQ) return;

    const float* hr = hidden + (size_t)row * CI;
    float a0 = 0.f, a1 = 0.f;
#pragma unroll
    for (int c = lane; c < CI; c += 32) {
        const float hv = hr[c];
        a0 += hv * W2[2 * c + 0];
        a1 += hv * W2[2 * c + 1];
    }
#pragma unroll
    for (int o = 16; o > 0; o >>= 1) {
        a0 += __shfl_down_sync(0xffffffff, a0, o);
        a1 += __shfl_down_sync(0xffffffff, a1, o);
    }
    if (lane == 0) {
        out[2 * row + 0] = a0 + b2[0];
        out[2 * row + 1] = a1 + b2[1];
    }
}

// rel_BN = attn.mean(-1).mean(1): softmax rows sum to 1 -> exactly 1/32.
__global__ void relfill_kernel(float* __restrict__ rel)
{
    const int i = blockIdx.x * 256 + threadIdx.x;
    if (i < MQ) rel[i] = 0.03125f;
}

// ---------------------------------------------------------------------------
extern "C" void kernel_launch(void* const* d_in, const int* in_sizes, int n_in,
                              void* d_out, int out_size)
{
    const float* vis  = (const float*)d_in[0];
    const float* text = (const float*)d_in[1];
    const float* Wq = (const float*)d_in[2];
    const float* bq = (const float*)d_in[3];
    const float* Wk = (const float*)d_in[4];
    const float* bk = (const float*)d_in[5];
    const float* Wv = (const float*)d_in[6];
    const float* bv = (const float*)d_in[7];
    const float* W1 = (const float*)d_in[8];
    const float* b1 = (const float*)d_in[9];
    const float* W2 = (const float*)d_in[10];
    const float* b2 = (const float*)d_in[11];
    float* out = (float*)d_out;

    float *q, *kv, *fused, *hidden, *bkv;
    __half2 *wkvP, *wqP, *w1P;
    cudaGetSymbolAddress((void**)&q,      g_q);
    cudaGetSymbolAddress((void**)&kv,     g_kv);
    cudaGetSymbolAddress((void**)&fused,  g_fused);
    cudaGetSymbolAddress((void**)&hidden, g_hidden);
    cudaGetSymbolAddress((void**)&wkvP,   g_wkvP);
    cudaGetSymbolAddress((void**)&wqP,    g_wqP);
    cudaGetSymbolAddress((void**)&w1P,    g_w1P);
    cudaGetSymbolAddress((void**)&bkv,    g_bkv);

    // Pack weights to fp16 k-pair-major; combine K|V. Biases concatenated D2D.
    pack_w_kernel<<<(CT/2 * CI + 255) / 256, 256>>>(Wk, wkvP, CT, CI, NKV, 0);
    pack_w_kernel<<<(CT/2 * CI + 255) / 256, 256>>>(Wv, wkvP, CT, CI, NKV, CI);
    pack_w_kernel<<<(CV/2 * CI + 255) / 256, 256>>>(Wq, wqP, CV, CI, CI, 0);
    pack_w_kernel<<<(CI/2 * CI + 255) / 256, 256>>>(W1, w1P, CI, CI, CI, 0);
    cudaMemcpyAsync(bkv,       bk, CI * sizeof(float), cudaMemcpyDeviceToDevice);
    cudaMemcpyAsync(bkv + CI,  bv, CI * sizeof(float), cudaMemcpyDeviceToDevice);

    // Combined K|V projection: [8192,512] @ [512,1536]
    gemm_f16_kernel<false><<<dim3(NKV / 128, MKV / 128), 256>>>(text, wkvP, bkv, kv, MKV, NKV, CT);
    // Q projection: [50176,768] @ [768,768]
    gemm_f16_kernel<false><<<dim3(CI / 128, MQ / 128), 256>>>(vis, wqP, bq, q, MQ, CI, CV);
    // Attention + residual
    attn_kernel<<<BATCH * NHEAD * 2, 224>>>(q, kv, vis, fused);
    // MLP hidden with fused quick-gelu: [50176,768] @ [768,768]
    gemm_f16_kernel<true><<<dim3(CI / 128, MQ / 128), 256>>>(fused, w1P, b1, hidden, MQ, CI, CI);
    // Head GEMV
    head_kernel<<<(MQ + 7) / 8, 256>>>(hidden, W2, b2, out);
    // rel_BN constant
    relfill_kernel<<<(MQ + 255) / 256, 256>>>(out + (size_t)MQ * 2);
}

// round 7
// speedup vs baseline: 4.0820x; 1.0193x over previous
#include <cuda_runtime.h>
#include <cuda_fp16.h>
#include <cstdint>
#include <math.h>

// Problem constants
#define BATCH 256
#define NV    196
#define LT    32
#define CV    768
#define CT    512
#define CI    768
#define NHEAD 12
#define DHEAD 64

#define MQ  (BATCH*NV)   // 50176
#define MKV (BATCH*LT)   // 8192
#define NKV 1536         // combined K|V projection width

// Scratch (allocation-free rule: __device__ globals)
__device__ float g_q[(size_t)MQ * CI];
__device__ float g_kv[(size_t)MKV * NKV];
__device__ float g_fused[(size_t)MQ * CI];
__device__ float g_hidden[(size_t)MQ * CI];
// fp16 weights pre-packed in mma-fragment order:
//   frag[tk][tn][lane] = uint2(b0,b1) for m16n8k16 tile (tk: k16 index, tn: n8 index)
__device__ uint2 g_wkvF[(size_t)(CT/16) * (NKV/8) * 32];
__device__ uint2 g_wqF[(size_t)(CV/16) * (CI/8) * 32];
__device__ uint2 g_w1F[(size_t)(CI/16) * (CI/8) * 32];
__device__ float g_bkv[NKV];

// ---------------------------------------------------------------------------
__device__ __forceinline__ void mma_f16(float* c, const unsigned* a, const unsigned* b) {
    asm volatile(
        "mma.sync.aligned.m16n8k16.row.col.f32.f16.f16.f32 "
        "{%0,%1,%2,%3}, {%4,%5,%6,%7}, {%8,%9}, {%0,%1,%2,%3};\n"
        : "+f"(c[0]), "+f"(c[1]), "+f"(c[2]), "+f"(c[3])
        : "r"(a[0]), "r"(a[1]), "r"(a[2]), "r"(a[3]), "r"(b[0]), "r"(b[1]));
}

// ---------------------------------------------------------------------------
// Pack fp32 weights [K,N] into fragment-order fp16:
// out[((tk*outNtiles + tnOff + tn))*32 + lane] = (b0,b1) per mma lane.
// ---------------------------------------------------------------------------
__global__ void __launch_bounds__(256)
pack_frag_kernel(const float* __restrict__ W, uint2* __restrict__ out,
                 int K, int N, int outNtiles, int tnOff)
{
    const int idx = blockIdx.x * 256 + threadIdx.x;
    const int total = (K / 16) * (N / 8) * 32;
    if (idx >= total) return;
    const int lane = idx & 31;
    const int tile = idx >> 5;
    const int ntiles = N / 8;
    const int tn = tile % ntiles;
    const int tk = tile / ntiles;
    const int g = lane >> 2, tig = lane & 3;
    const int n = tn * 8 + g;
    const int k0 = tk * 16 + 2 * tig;
    const __half2 b0 = __floats2half2_rn(W[(size_t)k0 * N + n], W[(size_t)(k0 + 1) * N + n]);
    const __half2 b1 = __floats2half2_rn(W[(size_t)(k0 + 8) * N + n], W[(size_t)(k0 + 9) * N + n]);
    uint2 r;
    r.x = *(const unsigned*)&b0;
    r.y = *(const unsigned*)&b1;
    out[((size_t)tk * outNtiles + tnOff + tn) * 32 + lane] = r;
}

// ---------------------------------------------------------------------------
// FP16 mma.sync GEMM. C = A[M,K](fp32) * W + bias (optional quick-gelu).
// W given in fragment-order (Bf). Block tile 128x256, 8 warps (2m x 4n),
// warp tile 64x64. B loaded global->regs (L2-resident), A staged in smem.
// Smem: As 128x20 half2 = 10,240 B. M%128==0, N%256==0, K%32==0.
// ---------------------------------------------------------------------------
#define AS2_STRIDE 20

template <bool GELU>
__global__ void __launch_bounds__(256)
gemm_f16_kernel(const float* __restrict__ A, const uint2* __restrict__ Bf,
                const float* __restrict__ bias, float* __restrict__ C,
                int M, int N, int K)
{
    __shared__ __half2 As[128 * AS2_STRIDE];

    const int tid = threadIdx.x;
    const int warp = tid >> 5, lane = tid & 31;
    const int g = lane >> 2, tig = lane & 3;
    const int wm = (warp >> 2) * 64;        // 0 or 64
    const int wn = (warp & 3) * 64;         // 0,64,128,192
    const int rowBase = blockIdx.y * 128;
    const int colBase = blockIdx.x * 256;
    const int Ntiles = N >> 3;
    const int tnBase = (colBase + wn) >> 3;

    float acc[4][8][4];
#pragma unroll
    for (int mt = 0; mt < 4; mt++)
#pragma unroll
        for (int nt = 0; nt < 8; nt++)
#pragma unroll
            for (int r = 0; r < 4; r++) acc[mt][nt][r] = 0.f;

    const int KT = K >> 5;
    float4 ar[4];

    // A tile: 128 rows x 32 fp32 = 1024 float4 (4/thread).
    auto ldg_a = [&](int kt) {
        const float* Ab = A + (size_t)rowBase * K + kt * 32;
#pragma unroll
        for (int i = 0; i < 4; i++) {
            const int f = tid + i * 256;
            const int r = f >> 3, c4 = (f & 7) * 4;
            ar[i] = *(const float4*)(Ab + (size_t)r * K + c4);
        }
    };

    ldg_a(0);

    for (int kt = 0; kt < KT; kt++) {
        if (kt) __syncthreads();
#pragma unroll
        for (int i = 0; i < 4; i++) {
            const int f = tid + i * 256;
            const int r = f >> 3, c2 = (f & 7) * 2;
            const __half2 h0 = __floats2half2_rn(ar[i].x, ar[i].y);
            const __half2 h1 = __floats2half2_rn(ar[i].z, ar[i].w);
            __half2* dst = &As[r * AS2_STRIDE + c2];
            dst[0] = h0; dst[1] = h1;
        }
        __syncthreads();

        if (kt + 1 < KT) ldg_a(kt + 1);   // overlap with MMA below

#pragma unroll
        for (int k16 = 0; k16 < 2; k16++) {
            const int tk = kt * 2 + k16;
            // B fragments straight from global (fragment-order, coalesced)
            uint2 bfr[8];
            const uint2* bp = Bf + ((size_t)tk * Ntiles + tnBase) * 32 + lane;
#pragma unroll
            for (int nt = 0; nt < 8; nt++) bfr[nt] = bp[nt * 32];
            // A fragments from smem
            const int kb2 = k16 * 8;
            unsigned a[4][4];
#pragma unroll
            for (int mt = 0; mt < 4; mt++) {
                const int m0 = wm + mt * 16 + g;
                a[mt][0] = *(const unsigned*)&As[m0 * AS2_STRIDE + kb2 + tig];
                a[mt][1] = *(const unsigned*)&As[(m0 + 8) * AS2_STRIDE + kb2 + tig];
                a[mt][2] = *(const unsigned*)&As[m0 * AS2_STRIDE + kb2 + 4 + tig];
                a[mt][3] = *(const unsigned*)&As[(m0 + 8) * AS2_STRIDE + kb2 + 4 + tig];
            }
#pragma unroll
            for (int mt = 0; mt < 4; mt++)
#pragma unroll
                for (int nt = 0; nt < 8; nt++)
                    mma_f16(acc[mt][nt], a[mt], (const unsigned*)&bfr[nt]);
        }
    }

    // epilogue: bias (+ optional quick-gelu), float2 stores
#pragma unroll
    for (int mt = 0; mt < 4; mt++) {
        const int r0 = rowBase + wm + mt * 16 + g;
        const int r1 = r0 + 8;
#pragma unroll
        for (int nt = 0; nt < 8; nt++) {
            const int c = colBase + wn + nt * 8 + tig * 2;
            const float b0 = bias[c], b1 = bias[c + 1];
            float v00 = acc[mt][nt][0] + b0, v01 = acc[mt][nt][1] + b1;
            float v10 = acc[mt][nt][2] + b0, v11 = acc[mt][nt][3] + b1;
            if (GELU) {
                v00 = v00 / (1.f + __expf(-1.702f * v00));
                v01 = v01 / (1.f + __expf(-1.702f * v01));
                v10 = v10 / (1.f + __expf(-1.702f * v10));
                v11 = v11 / (1.f + __expf(-1.702f * v11));
            }
            *(float2*)(C + (size_t)r0 * N + c) = make_float2(v00, v01);
            *(float2*)(C + (size_t)r1 * N + c) = make_float2(v10, v11);
        }
    }
}

// ---------------------------------------------------------------------------
// Fused attention + residual. 2 threads per query (each owns 32 of D=64).
// kvbuf is the combined [MKV][1536] projection: K at h*64, V at 768 + h*64.
// ---------------------------------------------------------------------------
__global__ void __launch_bounds__(224)
attn_kernel(const float* __restrict__ q, const float* __restrict__ kvbuf,
            const float* __restrict__ vis, float* __restrict__ fused)
{
    __shared__ float ks[LT * DHEAD];
    __shared__ float vs[LT * DHEAD];

    const int bh = blockIdx.x >> 1;
    const int chunk = blockIdx.x & 1;
    const int b = bh / NHEAD;
    const int h = bh % NHEAD;
    const int tid = threadIdx.x;

    const float* kb = kvbuf + (size_t)b * LT * NKV + h * DHEAD;
    const float* vb = kb + 768;
    for (int f = tid; f < 512; f += 224) {
        const int l = f >> 4, d4 = f & 15;
        ((float4*)ks)[l * 16 + d4] = *(const float4*)(kb + (size_t)l * NKV + d4 * 4);
        ((float4*)vs)[l * 16 + d4] = *(const float4*)(vb + (size_t)l * NKV + d4 * 4);
    }
    __syncthreads();

    const bool active = tid < 196;
    const int qi = active ? (tid >> 1) : 97;
    const int half = (tid & 1) * 32;
    const int n = chunk * 98 + qi;
    const size_t rowOff = (size_t)b * NV + n;

    const float* qrow = q + rowOff * CI + h * DHEAD + half;
    float4 q4[8];
#pragma unroll
    for (int i = 0; i < 8; i++) q4[i] = *(const float4*)(qrow + i * 4);

    float s[LT];
#pragma unroll
    for (int l = 0; l < LT; l++) s[l] = 0.f;

#pragma unroll
    for (int i = 0; i < 8; i++) {
#pragma unroll
        for (int l = 0; l < LT; l++) {
            const float4 k4 = *(const float4*)(ks + l * DHEAD + half + i * 4);
            s[l] += q4[i].x * k4.x + q4[i].y * k4.y + q4[i].z * k4.z + q4[i].w * k4.w;
        }
    }
#pragma unroll
    for (int l = 0; l < LT; l++)
        s[l] += __shfl_xor_sync(0xffffffff, s[l], 1);

    float mx = -1e30f;
#pragma unroll
    for (int l = 0; l < LT; l++) { s[l] *= 0.125f; mx = fmaxf(mx, s[l]); }
    float sum = 0.f;
#pragma unroll
    for (int l = 0; l < LT; l++) { s[l] = __expf(s[l] - mx); sum += s[l]; }
    const float inv = 1.f / sum;
#pragma unroll
    for (int l = 0; l < LT; l++) s[l] *= inv;

    const float* visrow = vis + rowOff * CV + h * DHEAD + half;
    float* frow = fused + rowOff * CI + h * DHEAD + half;
#pragma unroll
    for (int i = 0; i < 8; i++) {
        float4 acc = make_float4(0.f, 0.f, 0.f, 0.f);
#pragma unroll
        for (int l = 0; l < LT; l++) {
            const float4 v4 = *(const float4*)(vs + l * DHEAD + half + i * 4);
            acc.x += s[l] * v4.x; acc.y += s[l] * v4.y;
            acc.z += s[l] * v4.z; acc.w += s[l] * v4.w;
        }
        const float4 r4 = *(const float4*)(visrow + i * 4);
        acc.x += r4.x; acc.y += r4.y; acc.z += r4.z; acc.w += r4.w;
        if (active) *(float4*)(frow + i * 4) = acc;
    }
}

// ---------------------------------------------------------------------------
// Head GEMV: logits[row, 0:2] = hidden[row,:] @ W2 + b2. One warp per row.
// ---------------------------------------------------------------------------
__global__ void __launch_bounds__(256)
head_kernel(const float* __restrict__ hidden, const float* __restrict__ W2,
            const float* __restrict__ b2, float* __restrict__ out)
{
    const int warp = threadIdx.x >> 5;
    const int lane = threadIdx.x & 31;
    const int row = blockIdx.x * 8 + warp;
    if (row >= MQ) return;

    const float* hr = hidden + (size_t)row * CI;
    float a0 = 0.f, a1 = 0.f;
#pragma unroll
    for (int c = lane; c < CI; c += 32) {
        const float hv = hr[c];
        a0 += hv * W2[2 * c + 0];
        a1 += hv * W2[2 * c + 1];
    }
#pragma unroll
    for (int o = 16; o > 0; o >>= 1) {
        a0 += __shfl_down_sync(0xffffffff, a0, o);
        a1 += __shfl_down_sync(0xffffffff, a1, o);
    }
    if (lane == 0) {
        out[2 * row + 0] = a0 + b2[0];
        out[2 * row + 1] = a1 + b2[1];
    }
}

// rel_BN = attn.mean(-1).mean(1): softmax rows sum to 1 -> exactly 1/32.
__global__ void relfill_kernel(float* __restrict__ rel)
{
    const int i = blockIdx.x * 256 + threadIdx.x;
    if (i < MQ) rel[i] = 0.03125f;
}

// ---------------------------------------------------------------------------
extern "C" void kernel_launch(void* const* d_in, const int* in_sizes, int n_in,
                              void* d_out, int out_size)
{
    const float* vis  = (const float*)d_in[0];
    const float* text = (const float*)d_in[1];
    const float* Wq = (const float*)d_in[2];
    const float* bq = (const float*)d_in[3];
    const float* Wk = (const float*)d_in[4];
    const float* bk = (const float*)d_in[5];
    const float* Wv = (const float*)d_in[6];
    const float* bv = (const float*)d_in[7];
    const float* W1 = (const float*)d_in[8];
    const float* b1 = (const float*)d_in[9];
    const float* W2 = (const float*)d_in[10];
    const float* b2 = (const float*)d_in[11];
    float* out = (float*)d_out;

    float *q, *kv, *fused, *hidden, *bkv;
    uint2 *wkvF, *wqF, *w1F;
    cudaGetSymbolAddress((void**)&q,      g_q);
    cudaGetSymbolAddress((void**)&kv,     g_kv);
    cudaGetSymbolAddress((void**)&fused,  g_fused);
    cudaGetSymbolAddress((void**)&hidden, g_hidden);
    cudaGetSymbolAddress((void**)&wkvF,   g_wkvF);
    cudaGetSymbolAddress((void**)&wqF,    g_wqF);
    cudaGetSymbolAddress((void**)&w1F,    g_w1F);
    cudaGetSymbolAddress((void**)&bkv,    g_bkv);

    // Pack weights to fragment-order fp16; combine K|V. Biases concatenated.
    pack_frag_kernel<<<(CT/16 * CI/8 * 32 + 255) / 256, 256>>>(Wk, wkvF, CT, CI, NKV/8, 0);
    pack_frag_kernel<<<(CT/16 * CI/8 * 32 + 255) / 256, 256>>>(Wv, wkvF, CT, CI, NKV/8, CI/8);
    pack_frag_kernel<<<(CV/16 * CI/8 * 32 + 255) / 256, 256>>>(Wq, wqF, CV, CI, CI/8, 0);
    pack_frag_kernel<<<(CI/16 * CI/8 * 32 + 255) / 256, 256>>>(W1, w1F, CI, CI, CI/8, 0);
    cudaMemcpyAsync(bkv,      bk, CI * sizeof(float), cudaMemcpyDeviceToDevice);
    cudaMemcpyAsync(bkv + CI, bv, CI * sizeof(float), cudaMemcpyDeviceToDevice);

    // Combined K|V projection: [8192,512] @ [512,1536]
    gemm_f16_kernel<false><<<dim3(NKV / 256, MKV / 128), 256>>>(text, wkvF, bkv, kv, MKV, NKV, CT);
    // Q projection: [50176,768] @ [768,768]
    gemm_f16_kernel<false><<<dim3(CI / 256, MQ / 128), 256>>>(vis, wqF, bq, q, MQ, CI, CV);
    // Attention + residual
    attn_kernel<<<BATCH * NHEAD * 2, 224>>>(q, kv, vis, fused);
    // MLP hidden with fused quick-gelu: [50176,768] @ [768,768]
    gemm_f16_kernel<true><<<dim3(CI / 256, MQ / 128), 256>>>(fused, w1F, b1, hidden, MQ, CI, CI);
    // Head GEMV
    head_kernel<<<(MQ + 7) / 8, 256>>>(hidden, W2, b2, out);
    // rel_BN constant
    relfill_kernel<<<(MQ + 255) / 256, 256>>>(out + (size_t)MQ * 2);
}

// round 8
// speedup vs baseline: 5.1715x; 1.2669x over previous
#include <cuda_runtime.h>
#include <cuda_fp16.h>
#include <cstdint>
#include <math.h>

// Problem constants
#define BATCH 256
#define NV    196
#define LT    32
#define CV    768
#define CT    512
#define CI    768
#define NHEAD 12
#define DHEAD 64

#define MQ  (BATCH*NV)   // 50176
#define MKV (BATCH*LT)   // 8192
#define NKV 1536         // combined K|V projection width

// Scratch (allocation-free rule: __device__ globals) — fp16 intermediates
__device__ __half2 g_qh[(size_t)MQ * (CI/2)];
__device__ __half2 g_kvh[(size_t)MKV * (NKV/2)];
__device__ __half2 g_fusedh[(size_t)MQ * (CI/2)];
__device__ float   g_part[(size_t)3 * MQ * 2];
// fp16 weights pre-packed in mma-fragment order
__device__ uint2 g_wkvF[(size_t)(CT/16) * (NKV/8) * 32];
__device__ uint2 g_wqF[(size_t)(CV/16) * (CI/8) * 32];
__device__ uint2 g_w1F[(size_t)(CI/16) * (CI/8) * 32];
__device__ float g_bkv[NKV];

// ---------------------------------------------------------------------------
__device__ __forceinline__ void mma_f16(float* c, const unsigned* a, const unsigned* b) {
    asm volatile(
        "mma.sync.aligned.m16n8k16.row.col.f32.f16.f16.f32 "
        "{%0,%1,%2,%3}, {%4,%5,%6,%7}, {%8,%9}, {%0,%1,%2,%3};\n"
        : "+f"(c[0]), "+f"(c[1]), "+f"(c[2]), "+f"(c[3])
        : "r"(a[0]), "r"(a[1]), "r"(a[2]), "r"(a[3]), "r"(b[0]), "r"(b[1]));
}
__device__ __forceinline__ unsigned h2u(const __half2 h) { return *(const unsigned*)&h; }

// ---------------------------------------------------------------------------
// Pack fp32 weights [K,N] into fragment-order fp16 (as in R7).
// ---------------------------------------------------------------------------
__global__ void __launch_bounds__(256)
pack_frag_kernel(const float* __restrict__ W, uint2* __restrict__ out,
                 int K, int N, int outNtiles, int tnOff)
{
    const int idx = blockIdx.x * 256 + threadIdx.x;
    const int total = (K / 16) * (N / 8) * 32;
    if (idx >= total) return;
    const int lane = idx & 31;
    const int tile = idx >> 5;
    const int ntiles = N / 8;
    const int tn = tile % ntiles;
    const int tk = tile / ntiles;
    const int g = lane >> 2, tig = lane & 3;
    const int n = tn * 8 + g;
    const int k0 = tk * 16 + 2 * tig;
    const __half2 b0 = __floats2half2_rn(W[(size_t)k0 * N + n], W[(size_t)(k0 + 1) * N + n]);
    const __half2 b1 = __floats2half2_rn(W[(size_t)(k0 + 8) * N + n], W[(size_t)(k0 + 9) * N + n]);
    uint2 r;
    r.x = h2u(b0);
    r.y = h2u(b1);
    out[((size_t)tk * outNtiles + tnOff + tn) * 32 + lane] = r;
}

// ---------------------------------------------------------------------------
// FP16 mma.sync GEMM. Block 128x256, 8 warps (2m x 4n), warp 64x64.
// A: fp32 or half2 (AHALF). B from fragment-order global. Epilogue:
//   MLPHEAD=0: bias -> half2 C store.
//   MLPHEAD=1: bias + quick-gelu + per-stripe W2 partial reduce -> part.
// ---------------------------------------------------------------------------
#define AS2_STRIDE 20

template <bool AHALF, bool MLPHEAD>
__global__ void __launch_bounds__(256)
gemm_f16_kernel(const void* __restrict__ Aptr, const uint2* __restrict__ Bf,
                const float* __restrict__ bias, __half2* __restrict__ Ch,
                const float* __restrict__ W2, float* __restrict__ part,
                int M, int N, int K)
{
    __shared__ __half2 As[128 * AS2_STRIDE];
    __shared__ float red[4][128][2];   // only used when MLPHEAD

    const int tid = threadIdx.x;
    const int warp = tid >> 5, lane = tid & 31;
    const int g = lane >> 2, tig = lane & 3;
    const int wm = (warp >> 2) * 64;
    const int wnIdx = warp & 3;
    const int wn = wnIdx * 64;
    const int rowBase = blockIdx.y * 128;
    const int colBase = blockIdx.x * 256;
    const int Ntiles = N >> 3;
    const int tnBase = (colBase + wn) >> 3;

    float acc[4][8][4];
#pragma unroll
    for (int mt = 0; mt < 4; mt++)
#pragma unroll
        for (int nt = 0; nt < 8; nt++)
#pragma unroll
            for (int r = 0; r < 4; r++) acc[mt][nt][r] = 0.f;

    const int KT = K >> 5;
    float4 ar[4];
    uint4 arh[2];

    auto ldg_a = [&](int kt) {
        if (AHALF) {
            const __half2* Ah = (const __half2*)Aptr;
#pragma unroll
            for (int i = 0; i < 2; i++) {
                const int f = tid + i * 256;
                const int r = f >> 2, c4 = (f & 3) * 4;
                arh[i] = *(const uint4*)(Ah + (size_t)(rowBase + r) * (K / 2) + kt * 16 + c4);
            }
        } else {
            const float* Af = (const float*)Aptr;
#pragma unroll
            for (int i = 0; i < 4; i++) {
                const int f = tid + i * 256;
                const int r = f >> 3, c4 = (f & 7) * 4;
                ar[i] = *(const float4*)(Af + (size_t)(rowBase + r) * K + kt * 32 + c4);
            }
        }
    };

    ldg_a(0);

    for (int kt = 0; kt < KT; kt++) {
        if (kt) __syncthreads();
        if (AHALF) {
#pragma unroll
            for (int i = 0; i < 2; i++) {
                const int f = tid + i * 256;
                const int r = f >> 2, c4 = (f & 3) * 4;
                *(uint4*)&As[r * AS2_STRIDE + c4] = arh[i];
            }
        } else {
#pragma unroll
            for (int i = 0; i < 4; i++) {
                const int f = tid + i * 256;
                const int r = f >> 3, c2 = (f & 7) * 2;
                const __half2 h0 = __floats2half2_rn(ar[i].x, ar[i].y);
                const __half2 h1 = __floats2half2_rn(ar[i].z, ar[i].w);
                __half2* dst = &As[r * AS2_STRIDE + c2];
                dst[0] = h0; dst[1] = h1;
            }
        }
        __syncthreads();

        if (kt + 1 < KT) ldg_a(kt + 1);

#pragma unroll
        for (int k16 = 0; k16 < 2; k16++) {
            const int tk = kt * 2 + k16;
            uint2 bfr[8];
            const uint2* bp = Bf + ((size_t)tk * Ntiles + tnBase) * 32 + lane;
#pragma unroll
            for (int nt = 0; nt < 8; nt++) bfr[nt] = bp[nt * 32];
            const int kb2 = k16 * 8;
            unsigned a[4][4];
#pragma unroll
            for (int mt = 0; mt < 4; mt++) {
                const int m0 = wm + mt * 16 + g;
                a[mt][0] = *(const unsigned*)&As[m0 * AS2_STRIDE + kb2 + tig];
                a[mt][1] = *(const unsigned*)&As[(m0 + 8) * AS2_STRIDE + kb2 + tig];
                a[mt][2] = *(const unsigned*)&As[m0 * AS2_STRIDE + kb2 + 4 + tig];
                a[mt][3] = *(const unsigned*)&As[(m0 + 8) * AS2_STRIDE + kb2 + 4 + tig];
            }
#pragma unroll
            for (int mt = 0; mt < 4; mt++)
#pragma unroll
                for (int nt = 0; nt < 8; nt++)
                    mma_f16(acc[mt][nt], a[mt], (const unsigned*)&bfr[nt]);
        }
    }

    if (!MLPHEAD) {
        // bias -> half2 C store
        const int Nh = N >> 1;
#pragma unroll
        for (int mt = 0; mt < 4; mt++) {
            const int r0 = rowBase + wm + mt * 16 + g;
            const int r1 = r0 + 8;
#pragma unroll
            for (int nt = 0; nt < 8; nt++) {
                const int c = colBase + wn + nt * 8 + tig * 2;
                const float b0 = bias[c], b1 = bias[c + 1];
                Ch[(size_t)r0 * Nh + (c >> 1)] =
                    __floats2half2_rn(acc[mt][nt][0] + b0, acc[mt][nt][1] + b1);
                Ch[(size_t)r1 * Nh + (c >> 1)] =
                    __floats2half2_rn(acc[mt][nt][2] + b0, acc[mt][nt][3] + b1);
            }
        }
    } else {
        // bias + quick-gelu + W2 partial dot, deterministic per-stripe reduce
#pragma unroll
        for (int mt = 0; mt < 4; mt++) {
            float h00 = 0.f, h01 = 0.f, h10 = 0.f, h11 = 0.f;
#pragma unroll
            for (int nt = 0; nt < 8; nt++) {
                const int c = colBase + wn + nt * 8 + tig * 2;
                const float b0 = bias[c], b1 = bias[c + 1];
                float v00 = acc[mt][nt][0] + b0, v01 = acc[mt][nt][1] + b1;
                float v10 = acc[mt][nt][2] + b0, v11 = acc[mt][nt][3] + b1;
                v00 = v00 / (1.f + __expf(-1.702f * v00));
                v01 = v01 / (1.f + __expf(-1.702f * v01));
                v10 = v10 / (1.f + __expf(-1.702f * v10));
                v11 = v11 / (1.f + __expf(-1.702f * v11));
                const float4 w4 = *(const float4*)(W2 + 2 * c);  // cols c, c+1
                h00 += v00 * w4.x + v01 * w4.z;
                h01 += v00 * w4.y + v01 * w4.w;
                h10 += v10 * w4.x + v11 * w4.z;
                h11 += v10 * w4.y + v11 * w4.w;
            }
#pragma unroll
            for (int o = 1; o <= 2; o <<= 1) {
                h00 += __shfl_xor_sync(0xffffffff, h00, o);
                h01 += __shfl_xor_sync(0xffffffff, h01, o);
                h10 += __shfl_xor_sync(0xffffffff, h10, o);
                h11 += __shfl_xor_sync(0xffffffff, h11, o);
            }
            if (tig == 0) {
                const int rl = wm + mt * 16 + g;
                red[wnIdx][rl][0] = h00; red[wnIdx][rl][1] = h01;
                red[wnIdx][rl + 8][0] = h10; red[wnIdx][rl + 8][1] = h11;
            }
        }
        __syncthreads();
        const int rl = tid >> 1, o = tid & 1;
        const float s = red[0][rl][o] + red[1][rl][o] + red[2][rl][o] + red[3][rl][o];
        part[(size_t)blockIdx.x * MQ * 2 + (size_t)(rowBase + rl) * 2 + o] = s;
    }
}

// ---------------------------------------------------------------------------
// Tensor-core attention + residual. One block per (b,h), 128 threads (4 warps).
// Q,K,V fp16 (adjacent-d half2 from GEMMs). S = Q K^T via mma; softmax fp32
// (h2exp, un-normalized P, 1/sum in epilogue); ctx = P V via mma; +vis; store
// fused as half2.
// ---------------------------------------------------------------------------
__global__ void __launch_bounds__(128)
attn_kernel(const __half2* __restrict__ qh, const __half2* __restrict__ kvh,
            const float* __restrict__ vis, __half2* __restrict__ fusedh)
{
    __shared__ __half2 Qs[208 * 36];   // [row][d2], stride 36
    __shared__ __half2 Ks[32 * 36];    // [l][d2],   stride 36
    __shared__ __half2 Vs[16 * 72];    // [l2][d] = (V[2l2][d], V[2l2+1][d]), stride 72

    const int bh = blockIdx.x;
    const int b = bh / NHEAD;
    const int h = bh % NHEAD;
    const int tid = threadIdx.x;
    const int warp = tid >> 5, lane = tid & 31;
    const int g = lane >> 2, tig = lane & 3;

    // ---- loads ----
    // Q: 196 rows x 8 uint4
    for (int f = tid; f < NV * 8; f += 128) {
        const int n = f >> 3, c = f & 7;
        *(uint4*)&Qs[n * 36 + c * 4] =
            *(const uint4*)(qh + ((size_t)b * NV + n) * 384 + h * 32 + c * 4);
    }
    // zero pad rows 196..207
    for (int f = tid; f < 12 * 36; f += 128) {
        Qs[196 * 36 + f] = __half2(__ushort_as_half(0), __ushort_as_half(0));
    }
    // K: 32 rows x 8 uint4
    for (int f = tid; f < 32 * 8; f += 128) {
        const int l = f >> 3, c = f & 7;
        *(uint4*)&Ks[l * 36 + c * 4] =
            *(const uint4*)(kvh + ((size_t)b * LT + l) * 768 + h * 32 + c * 4);
    }
    // V: repack to half2-over-l
    __half* Vsh = (__half*)Vs;
    for (int f = tid; f < 32 * 32; f += 128) {
        const int l = f >> 5, d2 = f & 31;
        const __half2 val = kvh[((size_t)b * LT + l) * 768 + 384 + h * 32 + d2];
        const int base = (l >> 1) * 144 + 4 * d2 + (l & 1);
        Vsh[base] = __low2half(val);
        Vsh[base + 2] = __high2half(val);
    }
    __syncthreads();

    for (int t = warp; t < 13; t += 4) {
        const int mb = t * 16;
        // ---- S = Q K^T (scaled) ----
        float sc[4][4];
#pragma unroll
        for (int tl = 0; tl < 4; tl++)
#pragma unroll
            for (int j = 0; j < 4; j++) sc[tl][j] = 0.f;
#pragma unroll
        for (int td = 0; td < 4; td++) {
            unsigned a[4];
            a[0] = *(const unsigned*)&Qs[(mb + g) * 36 + 8 * td + tig];
            a[1] = *(const unsigned*)&Qs[(mb + 8 + g) * 36 + 8 * td + tig];
            a[2] = *(const unsigned*)&Qs[(mb + g) * 36 + 8 * td + tig + 4];
            a[3] = *(const unsigned*)&Qs[(mb + 8 + g) * 36 + 8 * td + tig + 4];
#pragma unroll
            for (int tl = 0; tl < 4; tl++) {
                unsigned bb[2];
                bb[0] = *(const unsigned*)&Ks[(8 * tl + g) * 36 + 8 * td + tig];
                bb[1] = *(const unsigned*)&Ks[(8 * tl + g) * 36 + 8 * td + tig + 4];
                mma_f16(sc[tl], a, bb);
            }
        }
        // ---- softmax (rows g and g+8 of this tile) ----
        float mx0 = -1e30f, mx1 = -1e30f;
#pragma unroll
        for (int tl = 0; tl < 4; tl++) {
#pragma unroll
            for (int j = 0; j < 4; j++) sc[tl][j] *= 0.125f;
            mx0 = fmaxf(mx0, fmaxf(sc[tl][0], sc[tl][1]));
            mx1 = fmaxf(mx1, fmaxf(sc[tl][2], sc[tl][3]));
        }
        mx0 = fmaxf(mx0, __shfl_xor_sync(0xffffffff, mx0, 1));
        mx0 = fmaxf(mx0, __shfl_xor_sync(0xffffffff, mx0, 2));
        mx1 = fmaxf(mx1, __shfl_xor_sync(0xffffffff, mx1, 1));
        mx1 = fmaxf(mx1, __shfl_xor_sync(0xffffffff, mx1, 2));
        __half2 plo[4], phi[4];
        float sum0 = 0.f, sum1 = 0.f;
#pragma unroll
        for (int tl = 0; tl < 4; tl++) {
            const __half2 e0 = h2exp(__floats2half2_rn(sc[tl][0] - mx0, sc[tl][1] - mx0));
            const __half2 e1 = h2exp(__floats2half2_rn(sc[tl][2] - mx1, sc[tl][3] - mx1));
            plo[tl] = e0; phi[tl] = e1;
            const float2 f0 = __half22float2(e0);
            const float2 f1 = __half22float2(e1);
            sum0 += f0.x + f0.y;
            sum1 += f1.x + f1.y;
        }
        sum0 += __shfl_xor_sync(0xffffffff, sum0, 1);
        sum0 += __shfl_xor_sync(0xffffffff, sum0, 2);
        sum1 += __shfl_xor_sync(0xffffffff, sum1, 1);
        sum1 += __shfl_xor_sync(0xffffffff, sum1, 2);
        const float inv0 = __fdividef(1.f, sum0);
        const float inv1 = __fdividef(1.f, sum1);
        // ---- ctx = P V ----
        float cc[8][4];
#pragma unroll
        for (int tn = 0; tn < 8; tn++)
#pragma unroll
            for (int j = 0; j < 4; j++) cc[tn][j] = 0.f;
#pragma unroll
        for (int tl2 = 0; tl2 < 2; tl2++) {
            unsigned a[4];
            a[0] = h2u(plo[2 * tl2]);
            a[1] = h2u(phi[2 * tl2]);
            a[2] = h2u(plo[2 * tl2 + 1]);
            a[3] = h2u(phi[2 * tl2 + 1]);
#pragma unroll
            for (int tn = 0; tn < 8; tn++) {
                unsigned bb[2];
                bb[0] = *(const unsigned*)&Vs[(8 * tl2 + tig) * 72 + 8 * tn + g];
                bb[1] = *(const unsigned*)&Vs[(8 * tl2 + tig + 4) * 72 + 8 * tn + g];
                mma_f16(cc[tn], a, bb);
            }
        }
        // ---- epilogue: normalize + residual + store half2 ----
        const int r0 = mb + g, r1 = mb + 8 + g;
        if (r0 < NV) {
            const size_t row = (size_t)b * NV + r0;
#pragma unroll
            for (int tn = 0; tn < 8; tn++) {
                const int d0 = 8 * tn + 2 * tig;
                const float2 vr = *(const float2*)(vis + row * CV + h * 64 + d0);
                fusedh[row * 384 + h * 32 + (d0 >> 1)] =
                    __floats2half2_rn(cc[tn][0] * inv0 + vr.x, cc[tn][1] * inv0 + vr.y);
            }
        }
        if (r1 < NV) {
            const size_t row = (size_t)b * NV + r1;
#pragma unroll
            for (int tn = 0; tn < 8; tn++) {
                const int d0 = 8 * tn + 2 * tig;
                const float2 vr = *(const float2*)(vis + row * CV + h * 64 + d0);
                fusedh[row * 384 + h * 32 + (d0 >> 1)] =
                    __floats2half2_rn(cc[tn][2] * inv1 + vr.x, cc[tn][3] * inv1 + vr.y);
            }
        }
    }
}

// ---------------------------------------------------------------------------
// Combine per-stripe head partials: out = b2 + part0 + part1 + part2.
// ---------------------------------------------------------------------------
__global__ void __launch_bounds__(256)
head_combine_kernel(const float* __restrict__ part, const float* __restrict__ b2,
                    float* __restrict__ out)
{
    const int idx = blockIdx.x * 256 + threadIdx.x;
    if (idx >= MQ * 2) return;
    const int o = idx & 1;
    out[idx] = b2[o] + part[idx] + part[(size_t)MQ * 2 + idx] + part[(size_t)2 * MQ * 2 + idx];
}

// rel_BN = attn.mean(-1).mean(1): softmax rows sum to 1 -> exactly 1/32.
__global__ void relfill_kernel(float* __restrict__ rel)
{
    const int i = blockIdx.x * 256 + threadIdx.x;
    if (i < MQ) rel[i] = 0.03125f;
}

// ---------------------------------------------------------------------------
extern "C" void kernel_launch(void* const* d_in, const int* in_sizes, int n_in,
                              void* d_out, int out_size)
{
    const float* vis  = (const float*)d_in[0];
    const float* text = (const float*)d_in[1];
    const float* Wq = (const float*)d_in[2];
    const float* bq = (const float*)d_in[3];
    const float* Wk = (const float*)d_in[4];
    const float* bk = (const float*)d_in[5];
    const float* Wv = (const float*)d_in[6];
    const float* bv = (const float*)d_in[7];
    const float* W1 = (const float*)d_in[8];
    const float* b1 = (const float*)d_in[9];
    const float* W2 = (const float*)d_in[10];
    const float* b2 = (const float*)d_in[11];
    float* out = (float*)d_out;

    __half2 *qh, *kvh, *fusedh;
    float *partp, *bkv;
    uint2 *wkvF, *wqF, *w1F;
    cudaGetSymbolAddress((void**)&qh,     g_qh);
    cudaGetSymbolAddress((void**)&kvh,    g_kvh);
    cudaGetSymbolAddress((void**)&fusedh, g_fusedh);
    cudaGetSymbolAddress((void**)&partp,  g_part);
    cudaGetSymbolAddress((void**)&wkvF,   g_wkvF);
    cudaGetSymbolAddress((void**)&wqF,    g_wqF);
    cudaGetSymbolAddress((void**)&w1F,    g_w1F);
    cudaGetSymbolAddress((void**)&bkv,    g_bkv);

    // Pack weights; combine K|V; concat biases.
    pack_frag_kernel<<<(CT/16 * CI/8 * 32 + 255) / 256, 256>>>(Wk, wkvF, CT, CI, NKV/8, 0);
    pack_frag_kernel<<<(CT/16 * CI/8 * 32 + 255) / 256, 256>>>(Wv, wkvF, CT, CI, NKV/8, CI/8);
    pack_frag_kernel<<<(CV/16 * CI/8 * 32 + 255) / 256, 256>>>(Wq, wqF, CV, CI, CI/8, 0);
    pack_frag_kernel<<<(CI/16 * CI/8 * 32 + 255) / 256, 256>>>(W1, w1F, CI, CI, CI/8, 0);
    cudaMemcpyAsync(bkv,      bk, CI * sizeof(float), cudaMemcpyDeviceToDevice);
    cudaMemcpyAsync(bkv + CI, bv, CI * sizeof(float), cudaMemcpyDeviceToDevice);

    // Combined K|V projection: [8192,512] @ [512,1536] -> fp16
    gemm_f16_kernel<false, false><<<dim3(NKV / 256, MKV / 128), 256>>>(
        text, wkvF, bkv, kvh, nullptr, nullptr, MKV, NKV, CT);
    // Q projection: [50176,768] @ [768,768] -> fp16
    gemm_f16_kernel<false, false><<<dim3(CI / 256, MQ / 128), 256>>>(
        vis, wqF, bq, qh, nullptr, nullptr, MQ, CI, CV);
    // Tensor attention + residual -> fused fp16
    attn_kernel<<<BATCH * NHEAD, 128>>>(qh, kvh, vis, fusedh);
    // MLP hidden GEMM with fused gelu + head partials (no hidden buffer)
    gemm_f16_kernel<true, true><<<dim3(CI / 256, MQ / 128), 256>>>(
        fusedh, w1F, b1, nullptr, W2, partp, MQ, CI, CI);
    // Combine head partials -> logits
    head_combine_kernel<<<(MQ * 2 + 255) / 256, 256>>>(partp, b2, out);
    // rel_BN constant
    relfill_kernel<<<(MQ + 255) / 256, 256>>>(out + (size_t)MQ * 2);
}

// round 9
// speedup vs baseline: 5.8236x; 1.1261x over previous
#include <cuda_runtime.h>
#include <cuda_fp16.h>
#include <cstdint>
#include <math.h>

// Problem constants
#define BATCH 256
#define NV    196
#define LT    32
#define CV    768
#define CT    512
#define CI    768
#define NHEAD 12
#define DHEAD 64

#define MQ  (BATCH*NV)   // 50176
#define MKV (BATCH*LT)   // 8192
#define NKV 1536         // combined K|V projection width

// Scratch (allocation-free rule: __device__ globals) — fp16 intermediates
__device__ __half2 g_qh[(size_t)MQ * (CI/2)];
__device__ __half2 g_kvh[(size_t)MKV * (NKV/2)];
__device__ __half2 g_fusedh[(size_t)MQ * (CI/2)];
__device__ float   g_part[(size_t)3 * MQ * 2];
// fp16 weights pre-packed in mma-fragment order
__device__ uint2 g_wkvF[(size_t)(CT/16) * (NKV/8) * 32];
__device__ uint2 g_wqF[(size_t)(CV/16) * (CI/8) * 32];
__device__ uint2 g_w1F[(size_t)(CI/16) * (CI/8) * 32];
__device__ float g_bkv[NKV];

// ---------------------------------------------------------------------------
__device__ __forceinline__ void mma_f16(float* c, const unsigned* a, const unsigned* b) {
    asm volatile(
        "mma.sync.aligned.m16n8k16.row.col.f32.f16.f16.f32 "
        "{%0,%1,%2,%3}, {%4,%5,%6,%7}, {%8,%9}, {%0,%1,%2,%3};\n"
        : "+f"(c[0]), "+f"(c[1]), "+f"(c[2]), "+f"(c[3])
        : "r"(a[0]), "r"(a[1]), "r"(a[2]), "r"(a[3]), "r"(b[0]), "r"(b[1]));
}
__device__ __forceinline__ unsigned h2u(const __half2 h) { return *(const unsigned*)&h; }
__device__ __forceinline__ void ldmatrix_x4(unsigned* r, unsigned addr) {
    asm volatile("ldmatrix.sync.aligned.m8n8.x4.shared.b16 {%0,%1,%2,%3}, [%4];"
        : "=r"(r[0]), "=r"(r[1]), "=r"(r[2]), "=r"(r[3]) : "r"(addr));
}

// ---------------------------------------------------------------------------
// Pack fp32 weights [K,N] into fragment-order fp16.
// ---------------------------------------------------------------------------
__global__ void __launch_bounds__(256)
pack_frag_kernel(const float* __restrict__ W, uint2* __restrict__ out,
                 int K, int N, int outNtiles, int tnOff)
{
    const int idx = blockIdx.x * 256 + threadIdx.x;
    const int total = (K / 16) * (N / 8) * 32;
    if (idx >= total) return;
    const int lane = idx & 31;
    const int tile = idx >> 5;
    const int ntiles = N / 8;
    const int tn = tile % ntiles;
    const int tk = tile / ntiles;
    const int g = lane >> 2, tig = lane & 3;
    const int n = tn * 8 + g;
    const int k0 = tk * 16 + 2 * tig;
    const __half2 b0 = __floats2half2_rn(W[(size_t)k0 * N + n], W[(size_t)(k0 + 1) * N + n]);
    const __half2 b1 = __floats2half2_rn(W[(size_t)(k0 + 8) * N + n], W[(size_t)(k0 + 9) * N + n]);
    uint2 r;
    r.x = h2u(b0);
    r.y = h2u(b1);
    out[((size_t)tk * outNtiles + tnOff + tn) * 32 + lane] = r;
}

// ---------------------------------------------------------------------------
// FP16 mma.sync GEMM. Block 128x256, 8 warps (2m x 4n), warp 64x64.
// A via ldmatrix.x4 from smem (stride-20-half2 -> conflict-free);
// B fragment-order from global with register double-buffering.
// ---------------------------------------------------------------------------
#define AS2_STRIDE 20

template <bool AHALF, bool MLPHEAD>
__global__ void __launch_bounds__(256)
gemm_f16_kernel(const void* __restrict__ Aptr, const uint2* __restrict__ Bf,
                const float* __restrict__ bias, __half2* __restrict__ Ch,
                const float* __restrict__ W2, float* __restrict__ part,
                int M, int N, int K)
{
    __shared__ __half2 As[128 * AS2_STRIDE];
    __shared__ float red[4][128][2];   // only used when MLPHEAD

    const int tid = threadIdx.x;
    const int warp = tid >> 5, lane = tid & 31;
    const int g = lane >> 2, tig = lane & 3;
    const int wm = (warp >> 2) * 64;
    const int wnIdx = warp & 3;
    const int wn = wnIdx * 64;
    const int rowBase = blockIdx.y * 128;
    const int colBase = blockIdx.x * 256;
    const int Ntiles = N >> 3;
    const int tnBase = (colBase + wn) >> 3;

    // ldmatrix per-lane address base: row = wm + (lane&7) + ((lane>>3)&1)*8,
    // col(half2) = (lane>>4)*4
    const int lmRow = wm + (lane & 7) + ((lane >> 3) & 1) * 8;
    const int lmCol = (lane >> 4) * 4;
    const unsigned lmBase =
        (unsigned)__cvta_generic_to_shared(&As[lmRow * AS2_STRIDE + lmCol]);

    float acc[4][8][4];
#pragma unroll
    for (int mt = 0; mt < 4; mt++)
#pragma unroll
        for (int nt = 0; nt < 8; nt++)
#pragma unroll
            for (int r = 0; r < 4; r++) acc[mt][nt][r] = 0.f;

    const int KT = K >> 5;
    const int TKT = KT * 2;
    float4 ar[4];
    uint4 arh[2];

    auto ldg_a = [&](int kt) {
        if (AHALF) {
            const __half2* Ah = (const __half2*)Aptr;
#pragma unroll
            for (int i = 0; i < 2; i++) {
                const int f = tid + i * 256;
                const int r = f >> 2, c4 = (f & 3) * 4;
                arh[i] = *(const uint4*)(Ah + (size_t)(rowBase + r) * (K / 2) + kt * 16 + c4);
            }
        } else {
            const float* Af = (const float*)Aptr;
#pragma unroll
            for (int i = 0; i < 4; i++) {
                const int f = tid + i * 256;
                const int r = f >> 3, c4 = (f & 7) * 4;
                ar[i] = *(const float4*)(Af + (size_t)(rowBase + r) * K + kt * 32 + c4);
            }
        }
    };

    uint2 bfr[2][8];
    {   // preload B fragments for tk = 0
        const uint2* bp = Bf + (size_t)tnBase * 32 + lane;
#pragma unroll
        for (int nt = 0; nt < 8; nt++) bfr[0][nt] = bp[nt * 32];
    }
    ldg_a(0);

    for (int kt = 0; kt < KT; kt++) {
        if (kt) __syncthreads();
        if (AHALF) {
#pragma unroll
            for (int i = 0; i < 2; i++) {
                const int f = tid + i * 256;
                const int r = f >> 2, c4 = (f & 3) * 4;
                *(uint4*)&As[r * AS2_STRIDE + c4] = arh[i];
            }
        } else {
#pragma unroll
            for (int i = 0; i < 4; i++) {
                const int f = tid + i * 256;
                const int r = f >> 3, c2 = (f & 7) * 2;
                const __half2 h0 = __floats2half2_rn(ar[i].x, ar[i].y);
                const __half2 h1 = __floats2half2_rn(ar[i].z, ar[i].w);
                __half2* dst = &As[r * AS2_STRIDE + c2];
                dst[0] = h0; dst[1] = h1;
            }
        }
        __syncthreads();

        if (kt + 1 < KT) ldg_a(kt + 1);

#pragma unroll
        for (int k16 = 0; k16 < 2; k16++) {
            const int tk = kt * 2 + k16;
            const int cur = tk & 1;
            // prefetch next k16's B fragments (hidden behind this step's MMAs)
            if (tk + 1 < TKT) {
                const uint2* bp = Bf + ((size_t)(tk + 1) * Ntiles + tnBase) * 32 + lane;
#pragma unroll
                for (int nt = 0; nt < 8; nt++) bfr[cur ^ 1][nt] = bp[nt * 32];
            }
            // A fragments via ldmatrix.x4 (one per 16-row subtile)
            unsigned a[4][4];
            const unsigned kOff = k16 * 8 * 4;   // 8 half2 = 32 bytes
#pragma unroll
            for (int mt = 0; mt < 4; mt++)
                ldmatrix_x4(a[mt], lmBase + mt * 16 * AS2_STRIDE * 4 + kOff);
#pragma unroll
            for (int mt = 0; mt < 4; mt++)
#pragma unroll
                for (int nt = 0; nt < 8; nt++)
                    mma_f16(acc[mt][nt], a[mt], (const unsigned*)&bfr[cur][nt]);
        }
    }

    if (!MLPHEAD) {
        const int Nh = N >> 1;
#pragma unroll
        for (int mt = 0; mt < 4; mt++) {
            const int r0 = rowBase + wm + mt * 16 + g;
            const int r1 = r0 + 8;
#pragma unroll
            for (int nt = 0; nt < 8; nt++) {
                const int c = colBase + wn + nt * 8 + tig * 2;
                const float b0 = bias[c], b1 = bias[c + 1];
                Ch[(size_t)r0 * Nh + (c >> 1)] =
                    __floats2half2_rn(acc[mt][nt][0] + b0, acc[mt][nt][1] + b1);
                Ch[(size_t)r1 * Nh + (c >> 1)] =
                    __floats2half2_rn(acc[mt][nt][2] + b0, acc[mt][nt][3] + b1);
            }
        }
    } else {
#pragma unroll
        for (int mt = 0; mt < 4; mt++) {
            float h00 = 0.f, h01 = 0.f, h10 = 0.f, h11 = 0.f;
#pragma unroll
            for (int nt = 0; nt < 8; nt++) {
                const int c = colBase + wn + nt * 8 + tig * 2;
                const float b0 = bias[c], b1 = bias[c + 1];
                float v00 = acc[mt][nt][0] + b0, v01 = acc[mt][nt][1] + b1;
                float v10 = acc[mt][nt][2] + b0, v11 = acc[mt][nt][3] + b1;
                v00 = v00 / (1.f + __expf(-1.702f * v00));
                v01 = v01 / (1.f + __expf(-1.702f * v01));
                v10 = v10 / (1.f + __expf(-1.702f * v10));
                v11 = v11 / (1.f + __expf(-1.702f * v11));
                const float4 w4 = *(const float4*)(W2 + 2 * c);
                h00 += v00 * w4.x + v01 * w4.z;
                h01 += v00 * w4.y + v01 * w4.w;
                h10 += v10 * w4.x + v11 * w4.z;
                h11 += v10 * w4.y + v11 * w4.w;
            }
#pragma unroll
            for (int o = 1; o <= 2; o <<= 1) {
                h00 += __shfl_xor_sync(0xffffffff, h00, o);
                h01 += __shfl_xor_sync(0xffffffff, h01, o);
                h10 += __shfl_xor_sync(0xffffffff, h10, o);
                h11 += __shfl_xor_sync(0xffffffff, h11, o);
            }
            if (tig == 0) {
                const int rl = wm + mt * 16 + g;
                red[wnIdx][rl][0] = h00; red[wnIdx][rl][1] = h01;
                red[wnIdx][rl + 8][0] = h10; red[wnIdx][rl + 8][1] = h11;
            }
        }
        __syncthreads();
        const int rl = tid >> 1, o = tid & 1;
        const float s = red[0][rl][o] + red[1][rl][o] + red[2][rl][o] + red[3][rl][o];
        part[(size_t)blockIdx.x * MQ * 2 + (size_t)(rowBase + rl) * 2 + o] = s;
    }
}

// ---------------------------------------------------------------------------
// Tensor-core attention + residual (unchanged from R8).
// ---------------------------------------------------------------------------
__global__ void __launch_bounds__(128)
attn_kernel(const __half2* __restrict__ qh, const __half2* __restrict__ kvh,
            const float* __restrict__ vis, __half2* __restrict__ fusedh)
{
    __shared__ __half2 Qs[208 * 36];
    __shared__ __half2 Ks[32 * 36];
    __shared__ __half2 Vs[16 * 72];

    const int bh = blockIdx.x;
    const int b = bh / NHEAD;
    const int h = bh % NHEAD;
    const int tid = threadIdx.x;
    const int warp = tid >> 5, lane = tid & 31;
    const int g = lane >> 2, tig = lane & 3;

    for (int f = tid; f < NV * 8; f += 128) {
        const int n = f >> 3, c = f & 7;
        *(uint4*)&Qs[n * 36 + c * 4] =
            *(const uint4*)(qh + ((size_t)b * NV + n) * 384 + h * 32 + c * 4);
    }
    for (int f = tid; f < 12 * 36; f += 128) {
        Qs[196 * 36 + f] = __half2(__ushort_as_half(0), __ushort_as_half(0));
    }
    for (int f = tid; f < 32 * 8; f += 128) {
        const int l = f >> 3, c = f & 7;
        *(uint4*)&Ks[l * 36 + c * 4] =
            *(const uint4*)(kvh + ((size_t)b * LT + l) * 768 + h * 32 + c * 4);
    }
    __half* Vsh = (__half*)Vs;
    for (int f = tid; f < 32 * 32; f += 128) {
        const int l = f >> 5, d2 = f & 31;
        const __half2 val = kvh[((size_t)b * LT + l) * 768 + 384 + h * 32 + d2];
        const int base = (l >> 1) * 144 + 4 * d2 + (l & 1);
        Vsh[base] = __low2half(val);
        Vsh[base + 2] = __high2half(val);
    }
    __syncthreads();

    for (int t = warp; t < 13; t += 4) {
        const int mb = t * 16;
        float sc[4][4];
#pragma unroll
        for (int tl = 0; tl < 4; tl++)
#pragma unroll
            for (int j = 0; j < 4; j++) sc[tl][j] = 0.f;
#pragma unroll
        for (int td = 0; td < 4; td++) {
            unsigned a[4];
            a[0] = *(const unsigned*)&Qs[(mb + g) * 36 + 8 * td + tig];
            a[1] = *(const unsigned*)&Qs[(mb + 8 + g) * 36 + 8 * td + tig];
            a[2] = *(const unsigned*)&Qs[(mb + g) * 36 + 8 * td + tig + 4];
            a[3] = *(const unsigned*)&Qs[(mb + 8 + g) * 36 + 8 * td + tig + 4];
#pragma unroll
            for (int tl = 0; tl < 4; tl++) {
                unsigned bb[2];
                bb[0] = *(const unsigned*)&Ks[(8 * tl + g) * 36 + 8 * td + tig];
                bb[1] = *(const unsigned*)&Ks[(8 * tl + g) * 36 + 8 * td + tig + 4];
                mma_f16(sc[tl], a, bb);
            }
        }
        float mx0 = -1e30f, mx1 = -1e30f;
#pragma unroll
        for (int tl = 0; tl < 4; tl++) {
#pragma unroll
            for (int j = 0; j < 4; j++) sc[tl][j] *= 0.125f;
            mx0 = fmaxf(mx0, fmaxf(sc[tl][0], sc[tl][1]));
            mx1 = fmaxf(mx1, fmaxf(sc[tl][2], sc[tl][3]));
        }
        mx0 = fmaxf(mx0, __shfl_xor_sync(0xffffffff, mx0, 1));
        mx0 = fmaxf(mx0, __shfl_xor_sync(0xffffffff, mx0, 2));
        mx1 = fmaxf(mx1, __shfl_xor_sync(0xffffffff, mx1, 1));
        mx1 = fmaxf(mx1, __shfl_xor_sync(0xffffffff, mx1, 2));
        __half2 plo[4], phi[4];
        float sum0 = 0.f, sum1 = 0.f;
#pragma unroll
        for (int tl = 0; tl < 4; tl++) {
            const __half2 e0 = h2exp(__floats2half2_rn(sc[tl][0] - mx0, sc[tl][1] - mx0));
            const __half2 e1 = h2exp(__floats2half2_rn(sc[tl][2] - mx1, sc[tl][3] - mx1));
            plo[tl] = e0; phi[tl] = e1;
            const float2 f0 = __half22float2(e0);
            const float2 f1 = __half22float2(e1);
            sum0 += f0.x + f0.y;
            sum1 += f1.x + f1.y;
        }
        sum0 += __shfl_xor_sync(0xffffffff, sum0, 1);
        sum0 += __shfl_xor_sync(0xffffffff, sum0, 2);
        sum1 += __shfl_xor_sync(0xffffffff, sum1, 1);
        sum1 += __shfl_xor_sync(0xffffffff, sum1, 2);
        const float inv0 = __fdividef(1.f, sum0);
        const float inv1 = __fdividef(1.f, sum1);
        float cc[8][4];
#pragma unroll
        for (int tn = 0; tn < 8; tn++)
#pragma unroll
            for (int j = 0; j < 4; j++) cc[tn][j] = 0.f;
#pragma unroll
        for (int tl2 = 0; tl2 < 2; tl2++) {
            unsigned a[4];
            a[0] = h2u(plo[2 * tl2]);
            a[1] = h2u(phi[2 * tl2]);
            a[2] = h2u(plo[2 * tl2 + 1]);
            a[3] = h2u(phi[2 * tl2 + 1]);
#pragma unroll
            for (int tn = 0; tn < 8; tn++) {
                unsigned bb[2];
                bb[0] = *(const unsigned*)&Vs[(8 * tl2 + tig) * 72 + 8 * tn + g];
                bb[1] = *(const unsigned*)&Vs[(8 * tl2 + tig + 4) * 72 + 8 * tn + g];
                mma_f16(cc[tn], a, bb);
            }
        }
        const int r0 = mb + g, r1 = mb + 8 + g;
        if (r0 < NV) {
            const size_t row = (size_t)b * NV + r0;
#pragma unroll
            for (int tn = 0; tn < 8; tn++) {
                const int d0 = 8 * tn + 2 * tig;
                const float2 vr = *(const float2*)(vis + row * CV + h * 64 + d0);
                fusedh[row * 384 + h * 32 + (d0 >> 1)] =
                    __floats2half2_rn(cc[tn][0] * inv0 + vr.x, cc[tn][1] * inv0 + vr.y);
            }
        }
        if (r1 < NV) {
            const size_t row = (size_t)b * NV + r1;
#pragma unroll
            for (int tn = 0; tn < 8; tn++) {
                const int d0 = 8 * tn + 2 * tig;
                const float2 vr = *(const float2*)(vis + row * CV + h * 64 + d0);
                fusedh[row * 384 + h * 32 + (d0 >> 1)] =
                    __floats2half2_rn(cc[tn][2] * inv1 + vr.x, cc[tn][3] * inv1 + vr.y);
            }
        }
    }
}

// ---------------------------------------------------------------------------
__global__ void __launch_bounds__(256)
head_combine_kernel(const float* __restrict__ part, const float* __restrict__ b2,
                    float* __restrict__ out)
{
    const int idx = blockIdx.x * 256 + threadIdx.x;
    if (idx >= MQ * 2) return;
    const int o = idx & 1;
    out[idx] = b2[o] + part[idx] + part[(size_t)MQ * 2 + idx] + part[(size_t)2 * MQ * 2 + idx];
}

// rel_BN = attn.mean(-1).mean(1): softmax rows sum to 1 -> exactly 1/32.
__global__ void relfill_kernel(float* __restrict__ rel)
{
    const int i = blockIdx.x * 256 + threadIdx.x;
    if (i < MQ) rel[i] = 0.03125f;
}

// ---------------------------------------------------------------------------
extern "C" void kernel_launch(void* const* d_in, const int* in_sizes, int n_in,
                              void* d_out, int out_size)
{
    const float* vis  = (const float*)d_in[0];
    const float* text = (const float*)d_in[1];
    const float* Wq = (const float*)d_in[2];
    const float* bq = (const float*)d_in[3];
    const float* Wk = (const float*)d_in[4];
    const float* bk = (const float*)d_in[5];
    const float* Wv = (const float*)d_in[6];
    const float* bv = (const float*)d_in[7];
    const float* W1 = (const float*)d_in[8];
    const float* b1 = (const float*)d_in[9];
    const float* W2 = (const float*)d_in[10];
    const float* b2 = (const float*)d_in[11];
    float* out = (float*)d_out;

    __half2 *qh, *kvh, *fusedh;
    float *partp, *bkv;
    uint2 *wkvF, *wqF, *w1F;
    cudaGetSymbolAddress((void**)&qh,     g_qh);
    cudaGetSymbolAddress((void**)&kvh,    g_kvh);
    cudaGetSymbolAddress((void**)&fusedh, g_fusedh);
    cudaGetSymbolAddress((void**)&partp,  g_part);
    cudaGetSymbolAddress((void**)&wkvF,   g_wkvF);
    cudaGetSymbolAddress((void**)&wqF,    g_wqF);
    cudaGetSymbolAddress((void**)&w1F,    g_w1F);
    cudaGetSymbolAddress((void**)&bkv,    g_bkv);

    pack_frag_kernel<<<(CT/16 * CI/8 * 32 + 255) / 256, 256>>>(Wk, wkvF, CT, CI, NKV/8, 0);
    pack_frag_kernel<<<(CT/16 * CI/8 * 32 + 255) / 256, 256>>>(Wv, wkvF, CT, CI, NKV/8, CI/8);
    pack_frag_kernel<<<(CV/16 * CI/8 * 32 + 255) / 256, 256>>>(Wq, wqF, CV, CI, CI/8, 0);
    pack_frag_kernel<<<(CI/16 * CI/8 * 32 + 255) / 256, 256>>>(W1, w1F, CI, CI, CI/8, 0);
    cudaMemcpyAsync(bkv,      bk, CI * sizeof(float), cudaMemcpyDeviceToDevice);
    cudaMemcpyAsync(bkv + CI, bv, CI * sizeof(float), cudaMemcpyDeviceToDevice);

    gemm_f16_kernel<false, false><<<dim3(NKV / 256, MKV / 128), 256>>>(
        text, wkvF, bkv, kvh, nullptr, nullptr, MKV, NKV, CT);
    gemm_f16_kernel<false, false><<<dim3(CI / 256, MQ / 128), 256>>>(
        vis, wqF, bq, qh, nullptr, nullptr, MQ, CI, CV);
    attn_kernel<<<BATCH * NHEAD, 128>>>(qh, kvh, vis, fusedh);
    gemm_f16_kernel<true, true><<<dim3(CI / 256, MQ / 128), 256>>>(
        fusedh, w1F, b1, nullptr, W2, partp, MQ, CI, CI);
    head_combine_kernel<<<(MQ * 2 + 255) / 256, 256>>>(partp, b2, out);
    relfill_kernel<<<(MQ + 255) / 256, 256>>>(out + (size_t)MQ * 2);
}